// round 2
// baseline (speedup 1.0000x reference)
#include <cuda_runtime.h>
#include <cuda_bf16.h>
#include <cstdint>

#define BB 4
#define SS 2048
#define DDIM 1024
#define HH 16
#define DH 64
#define MM (BB*SS)

// Head-major scratch [B,H,S,Dh] fp32 (allocation-free: __device__ globals)
__device__ float g_Qh[(size_t)BB*HH*SS*DH];
__device__ float g_Kh[(size_t)BB*HH*SS*DH];
__device__ float g_Vh[(size_t)BB*HH*SS*DH];

__device__ __forceinline__ uint32_t f2tf(float x){
    uint32_t y; asm("cvt.rna.tf32.f32 %0, %1;" : "=r"(y) : "f"(x)); return y;
}
__device__ __forceinline__ float ex2f(float x){
    float y; asm("ex2.approx.ftz.f32 %0, %1;" : "=f"(y) : "f"(x)); return y;
}
__device__ __forceinline__ void mma8(float* d, const uint32_t* a, const uint32_t* b){
    asm volatile(
        "mma.sync.aligned.m16n8k8.row.col.f32.tf32.tf32.f32 "
        "{%0,%1,%2,%3},{%4,%5,%6,%7},{%8,%9},{%0,%1,%2,%3};\n"
        : "+f"(d[0]), "+f"(d[1]), "+f"(d[2]), "+f"(d[3])
        : "r"(a[0]), "r"(a[1]), "r"(a[2]), "r"(a[3]), "r"(b[0]), "r"(b[1]));
}

// ============================================================================
// Projection: Out[b,h,s,d] = sum_k X[m,k] * W[n,k],  m=b*S+s, n=h*64+d
// CTA tile 128x64, BK=16, 8 warps (4x2), warp tile 32x32, tf32 mma m16n8k8.
// blockIdx.z selects which projection (0=Q, 1=K, 2=V) — one fused launch.
// ============================================================================
__global__ __launch_bounds__(256) void proj_kernel(const float* __restrict__ Xq,
                                                   const float* __restrict__ Xk,
                                                   const float* __restrict__ Xv,
                                                   const float* __restrict__ Wq,
                                                   const float* __restrict__ Wk,
                                                   const float* __restrict__ Wv){
    __shared__ uint32_t Xs[128][17];
    __shared__ uint32_t Ws[16][68];

    const int which = blockIdx.z;
    const float* X = (which == 0) ? Xq : (which == 1) ? Xk : Xv;
    const float* W = (which == 0) ? Wq : (which == 1) ? Wk : Wv;
    float* Out     = (which == 0) ? g_Qh : (which == 1) ? g_Kh : g_Vh;

    const int tid  = threadIdx.x;
    const int wid  = tid >> 5, lane = tid & 31;
    const int g    = lane >> 2, tig = lane & 3;
    const int wm   = wid & 3,  wn  = wid >> 2;
    const int m0   = blockIdx.y * 128;
    const int n0   = blockIdx.x * 64;

    float acc[2][4][4];
    #pragma unroll
    for (int i=0;i<2;i++)
        #pragma unroll
        for (int j=0;j<4;j++)
            #pragma unroll
            for (int c=0;c<4;c++) acc[i][j][c]=0.f;

    for (int kt = 0; kt < DDIM; kt += 16){
        // X tile 128x16 (512 float4, 2 per thread)
        #pragma unroll
        for (int i=0;i<2;i++){
            int idx = tid + i*256;
            int row = idx >> 2, c4 = idx & 3;
            float4 v = *(const float4*)(X + (size_t)(m0+row)*DDIM + kt + c4*4);
            Xs[row][c4*4+0]=f2tf(v.x); Xs[row][c4*4+1]=f2tf(v.y);
            Xs[row][c4*4+2]=f2tf(v.z); Xs[row][c4*4+3]=f2tf(v.w);
        }
        // W tile 64x16 transposed into Ws[k][n] (256 float4, 1 per thread)
        {
            int row = tid >> 2, c4 = tid & 3;
            float4 v = *(const float4*)(W + (size_t)(n0+row)*DDIM + kt + c4*4);
            Ws[c4*4+0][row]=f2tf(v.x); Ws[c4*4+1][row]=f2tf(v.y);
            Ws[c4*4+2][row]=f2tf(v.z); Ws[c4*4+3][row]=f2tf(v.w);
        }
        __syncthreads();

        #pragma unroll
        for (int ks=0; ks<2; ks++){
            const int kb = ks*8;
            uint32_t a[2][4], b[4][2];
            #pragma unroll
            for (int mt=0; mt<2; mt++){
                int r = wm*32 + mt*16;
                a[mt][0]=Xs[r+g  ][kb+tig  ];
                a[mt][1]=Xs[r+g+8][kb+tig  ];
                a[mt][2]=Xs[r+g  ][kb+tig+4];
                a[mt][3]=Xs[r+g+8][kb+tig+4];
            }
            #pragma unroll
            for (int nt=0; nt<4; nt++){
                int n = wn*32 + nt*8 + g;
                b[nt][0]=Ws[kb+tig  ][n];
                b[nt][1]=Ws[kb+tig+4][n];
            }
            #pragma unroll
            for (int mt=0;mt<2;mt++)
                #pragma unroll
                for (int nt=0;nt<4;nt++)
                    mma8(acc[mt][nt], a[mt], b[nt]);
        }
        __syncthreads();
    }

    // Epilogue: head-major store. n0 is a multiple of 64 -> single head per CTA.
    const int h = n0 >> 6;
    #pragma unroll
    for (int mt=0;mt<2;mt++){
        #pragma unroll
        for (int half=0; half<2; half++){
            int m  = m0 + wm*32 + mt*16 + g + half*8;
            int b_ = m >> 11;             // m / 2048
            int s  = m & (SS-1);
            float* orow = Out + (((size_t)(b_*HH + h))*SS + s)*DH;
            #pragma unroll
            for (int nt=0; nt<4; nt++){
                int d = wn*32 + nt*8 + tig*2;   // local d within head
                float2 v;
                v.x = acc[mt][nt][half*2+0];
                v.y = acc[mt][nt][half*2+1];
                *(float2*)(orow + d) = v;
            }
        }
    }
}

// ============================================================================
// Flash attention: one CTA per (qblock=64, h, b). 4 warps x 16 q-rows.
// tf32 mma; P routed through the K smem region (dead after QK^T).
// ============================================================================
__global__ __launch_bounds__(128) void attn_kernel(float* __restrict__ out){
    __shared__ uint32_t Ks[64][65];   // K tile; reused as P tile after QK
    __shared__ uint32_t Vs[64][65];

    const int tid = threadIdx.x;
    const int w   = tid >> 5, lane = tid & 31;
    const int g   = lane >> 2, tig = lane & 3;
    const int q0  = blockIdx.x * 64;
    const int h   = blockIdx.y, b = blockIdx.z;
    const int w16 = w * 16;
    const size_t headoff = ((size_t)(b*HH + h))*SS*DH;
    const float* Qg = g_Qh + headoff + (size_t)q0*DH;
    const float* Kg = g_Kh + headoff;
    const float* Vg = g_Vh + headoff;
    const float L2E = 1.44269504088896340736f;
    const float NEG_INF = __int_as_float(0xff800000);

    // ---- Stage Q (scaled by 1/sqrt(64)=0.125) into Ks, extract A fragments
    #pragma unroll
    for (int i=0;i<8;i++){
        int idx = tid + i*128;          // 1024 float4 = 64 rows x 16
        int row = idx >> 4, c4 = idx & 15;
        float4 v = *(const float4*)(Qg + (size_t)row*DH + c4*4);
        Ks[row][c4*4+0]=f2tf(v.x*0.125f); Ks[row][c4*4+1]=f2tf(v.y*0.125f);
        Ks[row][c4*4+2]=f2tf(v.z*0.125f); Ks[row][c4*4+3]=f2tf(v.w*0.125f);
    }
    __syncthreads();
    uint32_t qa[8][4];
    #pragma unroll
    for (int ks=0; ks<8; ks++){
        int kb = ks*8;
        qa[ks][0]=Ks[w16+g  ][kb+tig  ];
        qa[ks][1]=Ks[w16+g+8][kb+tig  ];
        qa[ks][2]=Ks[w16+g  ][kb+tig+4];
        qa[ks][3]=Ks[w16+g+8][kb+tig+4];
    }

    float Oacc[8][4];
    #pragma unroll
    for (int nt=0;nt<8;nt++)
        #pragma unroll
        for (int c=0;c<4;c++) Oacc[nt][c]=0.f;
    float mr0 = NEG_INF, mr1 = NEG_INF, l0 = 0.f, l1 = 0.f;

    for (int t0 = 0; t0 < SS; t0 += 64){
        __syncthreads();   // prev PV done / Q frags read before overwrite
        // ---- Load K,V tiles (64x64 each) as tf32
        #pragma unroll
        for (int i=0;i<8;i++){
            int idx = tid + i*128;
            int row = idx >> 4, c4 = idx & 15;
            float4 kv = *(const float4*)(Kg + (size_t)(t0+row)*DH + c4*4);
            Ks[row][c4*4+0]=f2tf(kv.x); Ks[row][c4*4+1]=f2tf(kv.y);
            Ks[row][c4*4+2]=f2tf(kv.z); Ks[row][c4*4+3]=f2tf(kv.w);
            float4 vv = *(const float4*)(Vg + (size_t)(t0+row)*DH + c4*4);
            Vs[row][c4*4+0]=f2tf(vv.x); Vs[row][c4*4+1]=f2tf(vv.y);
            Vs[row][c4*4+2]=f2tf(vv.z); Vs[row][c4*4+3]=f2tf(vv.w);
        }
        __syncthreads();

        // ---- S = Q K^T (16x64 per warp)
        float S[8][4];
        #pragma unroll
        for (int nt=0;nt<8;nt++)
            #pragma unroll
            for (int c=0;c<4;c++) S[nt][c]=0.f;
        #pragma unroll
        for (int ks=0; ks<8; ks++){
            const int kb = ks*8;
            #pragma unroll
            for (int nt=0; nt<8; nt++){
                uint32_t bfr[2];
                bfr[0]=Ks[nt*8+g][kb+tig  ];
                bfr[1]=Ks[nt*8+g][kb+tig+4];
                mma8(S[nt], qa[ks], bfr);
            }
        }

        // ---- Online softmax (rows g and g+8 per thread)
        float rmax0 = NEG_INF, rmax1 = NEG_INF;
        #pragma unroll
        for (int nt=0;nt<8;nt++){
            rmax0 = fmaxf(rmax0, fmaxf(S[nt][0], S[nt][1]));
            rmax1 = fmaxf(rmax1, fmaxf(S[nt][2], S[nt][3]));
        }
        rmax0 = fmaxf(rmax0, __shfl_xor_sync(0xffffffffu, rmax0, 1));
        rmax0 = fmaxf(rmax0, __shfl_xor_sync(0xffffffffu, rmax0, 2));
        rmax1 = fmaxf(rmax1, __shfl_xor_sync(0xffffffffu, rmax1, 1));
        rmax1 = fmaxf(rmax1, __shfl_xor_sync(0xffffffffu, rmax1, 2));
        float mn0 = fmaxf(mr0, rmax0), mn1 = fmaxf(mr1, rmax1);
        float al0 = ex2f((mr0 - mn0)*L2E);
        float al1 = ex2f((mr1 - mn1)*L2E);
        mr0 = mn0; mr1 = mn1;

        float rs0 = 0.f, rs1 = 0.f;
        #pragma unroll
        for (int nt=0;nt<8;nt++){
            S[nt][0] = ex2f((S[nt][0]-mn0)*L2E); rs0 += S[nt][0];
            S[nt][1] = ex2f((S[nt][1]-mn0)*L2E); rs0 += S[nt][1];
            S[nt][2] = ex2f((S[nt][2]-mn1)*L2E); rs1 += S[nt][2];
            S[nt][3] = ex2f((S[nt][3]-mn1)*L2E); rs1 += S[nt][3];
        }
        rs0 += __shfl_xor_sync(0xffffffffu, rs0, 1);
        rs0 += __shfl_xor_sync(0xffffffffu, rs0, 2);
        rs1 += __shfl_xor_sync(0xffffffffu, rs1, 1);
        rs1 += __shfl_xor_sync(0xffffffffu, rs1, 2);
        l0 = l0*al0 + rs0;
        l1 = l1*al1 + rs1;
        #pragma unroll
        for (int nt=0;nt<8;nt++){
            Oacc[nt][0]*=al0; Oacc[nt][1]*=al0;
            Oacc[nt][2]*=al1; Oacc[nt][3]*=al1;
        }

        // ---- Write P into Ks region (all warps must be done reading K first)
        __syncthreads();
        #pragma unroll
        for (int nt=0;nt<8;nt++){
            int c0 = nt*8 + tig*2;
            Ks[w16+g  ][c0  ] = f2tf(S[nt][0]);
            Ks[w16+g  ][c0+1] = f2tf(S[nt][1]);
            Ks[w16+g+8][c0  ] = f2tf(S[nt][2]);
            Ks[w16+g+8][c0+1] = f2tf(S[nt][3]);
        }
        __syncwarp();

        // ---- O += P V
        #pragma unroll
        for (int ks=0; ks<8; ks++){
            const int kb = ks*8;
            uint32_t pa[4];
            pa[0]=Ks[w16+g  ][kb+tig  ];
            pa[1]=Ks[w16+g+8][kb+tig  ];
            pa[2]=Ks[w16+g  ][kb+tig+4];
            pa[3]=Ks[w16+g+8][kb+tig+4];
            #pragma unroll
            for (int nt=0; nt<8; nt++){
                uint32_t bv[2];
                bv[0]=Vs[kb+tig  ][nt*8+g];
                bv[1]=Vs[kb+tig+4][nt*8+g];
                mma8(Oacc[nt], pa, bv);
            }
        }
    }

    // ---- Epilogue: out[b, s, h*64+d] = O / l
    float inv0 = 1.f / l0, inv1 = 1.f / l1;
    int s0 = q0 + w16 + g;
    #pragma unroll
    for (int nt=0;nt<8;nt++){
        int d = nt*8 + tig*2;
        float2 v0; v0.x = Oacc[nt][0]*inv0; v0.y = Oacc[nt][1]*inv0;
        *(float2*)(out + ((size_t)b*SS + s0  )*DDIM + h*DH + d) = v0;
        float2 v1; v1.x = Oacc[nt][2]*inv1; v1.y = Oacc[nt][3]*inv1;
        *(float2*)(out + ((size_t)b*SS + s0+8)*DDIM + h*DH + d) = v1;
    }
}

extern "C" void kernel_launch(void* const* d_in, const int* in_sizes, int n_in,
                              void* d_out, int out_size){
    const float* q  = (const float*)d_in[0];
    const float* k  = (const float*)d_in[1];
    const float* v  = (const float*)d_in[2];
    const float* Wq = (const float*)d_in[3];
    const float* Wk = (const float*)d_in[4];
    const float* Wv = (const float*)d_in[5];

    dim3 pg(DDIM/64, MM/128, 3);   // (16, 64, 3) — fused Q/K/V projections
    proj_kernel<<<pg, 256>>>(q, k, v, Wq, Wk, Wv);

    dim3 ag(SS/64, HH, BB);        // (32, 16, 4)
    attn_kernel<<<ag, 128>>>((float*)d_out);
}

// round 5
// speedup vs baseline: 1.5651x; 1.5651x over previous
#include <cuda_runtime.h>
#include <cuda_bf16.h>
#include <cstdint>

#define BB 4
#define SS 2048
#define DDIM 1024
#define HH 16
#define DH 64
#define MM (BB*SS)

// Head-major scratch [B,H,S,Dh] fp32 (allocation-free: __device__ globals)
__device__ float g_Qh[(size_t)BB*HH*SS*DH];
__device__ float g_Kh[(size_t)BB*HH*SS*DH];
__device__ float g_Vh[(size_t)BB*HH*SS*DH];

__device__ __forceinline__ uint32_t f2tf(float x){
    uint32_t y; asm("cvt.rna.tf32.f32 %0, %1;" : "=r"(y) : "f"(x)); return y;
}
__device__ __forceinline__ float ex2f(float x){
    float y; asm("ex2.approx.ftz.f32 %0, %1;" : "=f"(y) : "f"(x)); return y;
}
__device__ __forceinline__ void mma8(float* d, const uint32_t* a, const uint32_t* b){
    asm volatile(
        "mma.sync.aligned.m16n8k8.row.col.f32.tf32.tf32.f32 "
        "{%0,%1,%2,%3},{%4,%5,%6,%7},{%8,%9},{%0,%1,%2,%3};\n"
        : "+f"(d[0]), "+f"(d[1]), "+f"(d[2]), "+f"(d[3])
        : "r"(a[0]), "r"(a[1]), "r"(a[2]), "r"(a[3]), "r"(b[0]), "r"(b[1]));
}

// ============================================================================
// Projection: Out[b,h,s,d] = sum_k X[m,k] * W[n,k],  m=b*S+s, n=h*64+d
// CTA tile 128x64, BK=16, 8 warps (4x2), warp tile 32x32, tf32 mma m16n8k8.
// blockIdx.z selects which projection (0=Q, 1=K, 2=V) — one fused launch.
// Xs pad 20 (20g mod 32 covers all multiples of 4 -> conflict-free A loads).
// ============================================================================
__global__ __launch_bounds__(256) void proj_kernel(const float* __restrict__ Xq,
                                                   const float* __restrict__ Xk,
                                                   const float* __restrict__ Xv,
                                                   const float* __restrict__ Wq,
                                                   const float* __restrict__ Wk,
                                                   const float* __restrict__ Wv){
    __shared__ uint32_t Xs[128][20];
    __shared__ uint32_t Ws[16][68];

    const int which = blockIdx.z;
    const float* X = (which == 0) ? Xq : (which == 1) ? Xk : Xv;
    const float* W = (which == 0) ? Wq : (which == 1) ? Wk : Wv;
    float* Out     = (which == 0) ? g_Qh : (which == 1) ? g_Kh : g_Vh;

    const int tid  = threadIdx.x;
    const int wid  = tid >> 5, lane = tid & 31;
    const int g    = lane >> 2, tig = lane & 3;
    const int wm   = wid & 3,  wn  = wid >> 2;
    const int m0   = blockIdx.y * 128;
    const int n0   = blockIdx.x * 64;

    float acc[2][4][4];
    #pragma unroll
    for (int i=0;i<2;i++)
        #pragma unroll
        for (int j=0;j<4;j++)
            #pragma unroll
            for (int c=0;c<4;c++) acc[i][j][c]=0.f;

    for (int kt = 0; kt < DDIM; kt += 16){
        // X tile 128x16 (512 float4, 2 per thread), vector STS
        #pragma unroll
        for (int i=0;i<2;i++){
            int idx = tid + i*256;
            int row = idx >> 2, c4 = idx & 3;
            float4 v = *(const float4*)(X + (size_t)(m0+row)*DDIM + kt + c4*4);
            *(uint4*)&Xs[row][c4*4] =
                make_uint4(f2tf(v.x), f2tf(v.y), f2tf(v.z), f2tf(v.w));
        }
        // W tile 64x16 transposed into Ws[k][n] (256 float4, 1 per thread)
        {
            int row = tid >> 2, c4 = tid & 3;
            float4 v = *(const float4*)(W + (size_t)(n0+row)*DDIM + kt + c4*4);
            Ws[c4*4+0][row]=f2tf(v.x); Ws[c4*4+1][row]=f2tf(v.y);
            Ws[c4*4+2][row]=f2tf(v.z); Ws[c4*4+3][row]=f2tf(v.w);
        }
        __syncthreads();

        #pragma unroll
        for (int ks=0; ks<2; ks++){
            const int kb = ks*8;
            uint32_t a[2][4], b[4][2];
            #pragma unroll
            for (int mt=0; mt<2; mt++){
                int r = wm*32 + mt*16;
                a[mt][0]=Xs[r+g  ][kb+tig  ];
                a[mt][1]=Xs[r+g+8][kb+tig  ];
                a[mt][2]=Xs[r+g  ][kb+tig+4];
                a[mt][3]=Xs[r+g+8][kb+tig+4];
            }
            #pragma unroll
            for (int nt=0; nt<4; nt++){
                int n = wn*32 + nt*8 + g;
                b[nt][0]=Ws[kb+tig  ][n];
                b[nt][1]=Ws[kb+tig+4][n];
            }
            #pragma unroll
            for (int mt=0;mt<2;mt++)
                #pragma unroll
                for (int nt=0;nt<4;nt++)
                    mma8(acc[mt][nt], a[mt], b[nt]);
        }
        __syncthreads();
    }

    // Epilogue: head-major store. n0 is a multiple of 64 -> single head per CTA.
    const int h = n0 >> 6;
    #pragma unroll
    for (int mt=0;mt<2;mt++){
        #pragma unroll
        for (int half=0; half<2; half++){
            int m  = m0 + wm*32 + mt*16 + g + half*8;
            int b_ = m >> 11;             // m / 2048
            int s  = m & (SS-1);
            float* orow = Out + (((size_t)(b_*HH + h))*SS + s)*DH;
            #pragma unroll
            for (int nt=0; nt<4; nt++){
                int d = wn*32 + nt*8 + tig*2;   // local d within head
                float2 v;
                v.x = acc[mt][nt][half*2+0];
                v.y = acc[mt][nt][half*2+1];
                *(float2*)(orow + d) = v;
            }
        }
    }
}

// ============================================================================
// Flash attention: one CTA per (qblock=64, h, b). 4 warps x 16 q-rows.
// tf32 mma. Pad 68 (== 4 mod 32) -> fragment loads (4g+tig) are conflict-free.
// V stored TRANSPOSED Vt[n][k] so PV B-loads are also conflict-free.
// P routed through the Ks region (dead after QK^T).
// ============================================================================
__global__ __launch_bounds__(128) void attn_kernel(float* __restrict__ out){
    __shared__ uint32_t Ks[64][68];   // K tile [s][k]; reused as P tile after QK
    __shared__ uint32_t Vt[64][68];   // V tile transposed [d][s]

    const int tid = threadIdx.x;
    const int w   = tid >> 5, lane = tid & 31;
    const int g   = lane >> 2, tig = lane & 3;
    const int q0  = blockIdx.x * 64;
    const int h   = blockIdx.y, b = blockIdx.z;
    const int w16 = w * 16;
    const size_t headoff = ((size_t)(b*HH + h))*SS*DH;
    const float* Qg = g_Qh + headoff + (size_t)q0*DH;
    const float* Kg = g_Kh + headoff;
    const float* Vg = g_Vh + headoff;
    const float L2E = 1.44269504088896340736f;
    const float NEG_INF = __int_as_float(0xff800000);

    // ---- Stage Q (scaled by 1/sqrt(64)=0.125) into Ks, extract A fragments
    #pragma unroll
    for (int i=0;i<8;i++){
        int idx = tid + i*128;          // 1024 float4 = 64 rows x 16
        int row = idx >> 4, c4 = idx & 15;
        float4 v = *(const float4*)(Qg + (size_t)row*DH + c4*4);
        *(uint4*)&Ks[row][c4*4] =
            make_uint4(f2tf(v.x*0.125f), f2tf(v.y*0.125f),
                       f2tf(v.z*0.125f), f2tf(v.w*0.125f));
    }
    __syncthreads();
    uint32_t qa[8][4];
    #pragma unroll
    for (int ks=0; ks<8; ks++){
        int kb = ks*8;
        qa[ks][0]=Ks[w16+g  ][kb+tig  ];
        qa[ks][1]=Ks[w16+g+8][kb+tig  ];
        qa[ks][2]=Ks[w16+g  ][kb+tig+4];
        qa[ks][3]=Ks[w16+g+8][kb+tig+4];
    }

    float Oacc[8][4];
    #pragma unroll
    for (int nt=0;nt<8;nt++)
        #pragma unroll
        for (int c=0;c<4;c++) Oacc[nt][c]=0.f;
    float mr0 = NEG_INF, mr1 = NEG_INF, l0 = 0.f, l1 = 0.f;

    for (int t0 = 0; t0 < SS; t0 += 64){
        __syncthreads();   // prev PV done / Q frags read before overwrite
        // ---- Load K tile [s][k] and V tile transposed [d][s]
        #pragma unroll
        for (int i=0;i<8;i++){
            int idx = tid + i*128;
            // K: row-major staging, vector STS (conflict-free per STS.128 phase)
            int row = idx >> 4, c4 = idx & 15;
            float4 kv = *(const float4*)(Kg + (size_t)(t0+row)*DH + c4*4);
            *(uint4*)&Ks[row][c4*4] =
                make_uint4(f2tf(kv.x), f2tf(kv.y), f2tf(kv.z), f2tf(kv.w));
            // V: transposed staging. rows follow lanes -> scatter STS conflict-free
            int vrow = idx & 63;        // s (token)
            int vc4  = idx >> 6;        // d group 0..15
            float4 vv = *(const float4*)(Vg + (size_t)(t0+vrow)*DH + vc4*4);
            Vt[vc4*4+0][vrow]=f2tf(vv.x);
            Vt[vc4*4+1][vrow]=f2tf(vv.y);
            Vt[vc4*4+2][vrow]=f2tf(vv.z);
            Vt[vc4*4+3][vrow]=f2tf(vv.w);
        }
        __syncthreads();

        // ---- S = Q K^T (16x64 per warp)
        float S[8][4];
        #pragma unroll
        for (int nt=0;nt<8;nt++)
            #pragma unroll
            for (int c=0;c<4;c++) S[nt][c]=0.f;
        #pragma unroll
        for (int ks=0; ks<8; ks++){
            const int kb = ks*8;
            #pragma unroll
            for (int nt=0; nt<8; nt++){
                uint32_t bfr[2];
                bfr[0]=Ks[nt*8+g][kb+tig  ];
                bfr[1]=Ks[nt*8+g][kb+tig+4];
                mma8(S[nt], qa[ks], bfr);
            }
        }

        // ---- Online softmax (rows g and g+8 per thread)
        float rmax0 = NEG_INF, rmax1 = NEG_INF;
        #pragma unroll
        for (int nt=0;nt<8;nt++){
            rmax0 = fmaxf(rmax0, fmaxf(S[nt][0], S[nt][1]));
            rmax1 = fmaxf(rmax1, fmaxf(S[nt][2], S[nt][3]));
        }
        rmax0 = fmaxf(rmax0, __shfl_xor_sync(0xffffffffu, rmax0, 1));
        rmax0 = fmaxf(rmax0, __shfl_xor_sync(0xffffffffu, rmax0, 2));
        rmax1 = fmaxf(rmax1, __shfl_xor_sync(0xffffffffu, rmax1, 1));
        rmax1 = fmaxf(rmax1, __shfl_xor_sync(0xffffffffu, rmax1, 2));
        float mn0 = fmaxf(mr0, rmax0), mn1 = fmaxf(mr1, rmax1);
        float al0 = ex2f((mr0 - mn0)*L2E);
        float al1 = ex2f((mr1 - mn1)*L2E);
        mr0 = mn0; mr1 = mn1;

        float rs0 = 0.f, rs1 = 0.f;
        #pragma unroll
        for (int nt=0;nt<8;nt++){
            S[nt][0] = ex2f((S[nt][0]-mn0)*L2E); rs0 += S[nt][0];
            S[nt][1] = ex2f((S[nt][1]-mn0)*L2E); rs0 += S[nt][1];
            S[nt][2] = ex2f((S[nt][2]-mn1)*L2E); rs1 += S[nt][2];
            S[nt][3] = ex2f((S[nt][3]-mn1)*L2E); rs1 += S[nt][3];
        }
        rs0 += __shfl_xor_sync(0xffffffffu, rs0, 1);
        rs0 += __shfl_xor_sync(0xffffffffu, rs0, 2);
        rs1 += __shfl_xor_sync(0xffffffffu, rs1, 1);
        rs1 += __shfl_xor_sync(0xffffffffu, rs1, 2);
        l0 = l0*al0 + rs0;
        l1 = l1*al1 + rs1;
        #pragma unroll
        for (int nt=0;nt<8;nt++){
            Oacc[nt][0]*=al0; Oacc[nt][1]*=al0;
            Oacc[nt][2]*=al1; Oacc[nt][3]*=al1;
        }

        // ---- Write P into Ks region (all warps must be done reading K first)
        __syncthreads();
        #pragma unroll
        for (int nt=0;nt<8;nt++){
            int c0 = nt*8 + tig*2;
            Ks[w16+g  ][c0  ] = f2tf(S[nt][0]);
            Ks[w16+g  ][c0+1] = f2tf(S[nt][1]);
            Ks[w16+g+8][c0  ] = f2tf(S[nt][2]);
            Ks[w16+g+8][c0+1] = f2tf(S[nt][3]);
        }
        __syncwarp();

        // ---- O += P V  (B operand from transposed Vt: conflict-free)
        #pragma unroll
        for (int ks=0; ks<8; ks++){
            const int kb = ks*8;
            uint32_t pa[4];
            pa[0]=Ks[w16+g  ][kb+tig  ];
            pa[1]=Ks[w16+g+8][kb+tig  ];
            pa[2]=Ks[w16+g  ][kb+tig+4];
            pa[3]=Ks[w16+g+8][kb+tig+4];
            #pragma unroll
            for (int nt=0; nt<8; nt++){
                uint32_t bv[2];
                bv[0]=Vt[nt*8+g][kb+tig  ];
                bv[1]=Vt[nt*8+g][kb+tig+4];
                mma8(Oacc[nt], pa, bv);
            }
        }
    }

    // ---- Epilogue: out[b, s, h*64+d] = O / l
    float inv0 = 1.f / l0, inv1 = 1.f / l1;
    int s0 = q0 + w16 + g;
    #pragma unroll
    for (int nt=0;nt<8;nt++){
        int d = nt*8 + tig*2;
        float2 v0; v0.x = Oacc[nt][0]*inv0; v0.y = Oacc[nt][1]*inv0;
        *(float2*)(out + ((size_t)b*SS + s0  )*DDIM + h*DH + d) = v0;
        float2 v1; v1.x = Oacc[nt][2]*inv1; v1.y = Oacc[nt][3]*inv1;
        *(float2*)(out + ((size_t)b*SS + s0+8)*DDIM + h*DH + d) = v1;
    }
}

extern "C" void kernel_launch(void* const* d_in, const int* in_sizes, int n_in,
                              void* d_out, int out_size){
    const float* q  = (const float*)d_in[0];
    const float* k  = (const float*)d_in[1];
    const float* v  = (const float*)d_in[2];
    const float* Wq = (const float*)d_in[3];
    const float* Wk = (const float*)d_in[4];
    const float* Wv = (const float*)d_in[5];

    dim3 pg(DDIM/64, MM/128, 3);   // (16, 64, 3) — fused Q/K/V projections
    proj_kernel<<<pg, 256>>>(q, k, v, Wq, Wk, Wv);

    dim3 ag(SS/64, HH, BB);        // (32, 16, 4)
    attn_kernel<<<ag, 128>>>((float*)d_out);
}

// round 8
// speedup vs baseline: 1.7440x; 1.1143x over previous
#include <cuda_runtime.h>
#include <cuda_bf16.h>
#include <cstdint>

#define BB 4
#define SS 2048
#define DDIM 1024
#define HH 16
#define DH 64
#define MM (BB*SS)

// Head-major scratch [B,H,S,Dh] fp32 (allocation-free: __device__ globals)
__device__ float g_Qh[(size_t)BB*HH*SS*DH];
__device__ float g_Kh[(size_t)BB*HH*SS*DH];
__device__ float g_Vh[(size_t)BB*HH*SS*DH];

__device__ __forceinline__ uint32_t f2tf(float x){
    uint32_t y; asm("cvt.rna.tf32.f32 %0, %1;" : "=r"(y) : "f"(x)); return y;
}
__device__ __forceinline__ float ex2f(float x){
    float y; asm("ex2.approx.ftz.f32 %0, %1;" : "=f"(y) : "f"(x)); return y;
}
__device__ __forceinline__ void mma8(float* d, const uint32_t* a, const uint32_t* b){
    asm volatile(
        "mma.sync.aligned.m16n8k8.row.col.f32.tf32.tf32.f32 "
        "{%0,%1,%2,%3},{%4,%5,%6,%7},{%8,%9},{%0,%1,%2,%3};\n"
        : "+f"(d[0]), "+f"(d[1]), "+f"(d[2]), "+f"(d[3])
        : "r"(a[0]), "r"(a[1]), "r"(a[2]), "r"(a[3]), "r"(b[0]), "r"(b[1]));
}

// ============================================================================
// Projection: Out[b,h,s,d] = sum_k X[m,k] * W[n,k],  m=b*S+s, n=h*64+d
// CTA tile 128x64, BK=16, 8 warps (4x2), warp tile 32x32, tf32 mma m16n8k8.
// blockIdx.z selects which projection (0=Q, 1=K, 2=V) — one fused launch.
// (unchanged from R5)
// ============================================================================
__global__ __launch_bounds__(256) void proj_kernel(const float* __restrict__ Xq,
                                                   const float* __restrict__ Xk,
                                                   const float* __restrict__ Xv,
                                                   const float* __restrict__ Wq,
                                                   const float* __restrict__ Wk,
                                                   const float* __restrict__ Wv){
    __shared__ uint32_t Xs[128][20];
    __shared__ uint32_t Ws[16][68];

    const int which = blockIdx.z;
    const float* X = (which == 0) ? Xq : (which == 1) ? Xk : Xv;
    const float* W = (which == 0) ? Wq : (which == 1) ? Wk : Wv;
    float* Out     = (which == 0) ? g_Qh : (which == 1) ? g_Kh : g_Vh;

    const int tid  = threadIdx.x;
    const int wid  = tid >> 5, lane = tid & 31;
    const int g    = lane >> 2, tig = lane & 3;
    const int wm   = wid & 3,  wn  = wid >> 2;
    const int m0   = blockIdx.y * 128;
    const int n0   = blockIdx.x * 64;

    float acc[2][4][4];
    #pragma unroll
    for (int i=0;i<2;i++)
        #pragma unroll
        for (int j=0;j<4;j++)
            #pragma unroll
            for (int c=0;c<4;c++) acc[i][j][c]=0.f;

    for (int kt = 0; kt < DDIM; kt += 16){
        #pragma unroll
        for (int i=0;i<2;i++){
            int idx = tid + i*256;
            int row = idx >> 2, c4 = idx & 3;
            float4 v = *(const float4*)(X + (size_t)(m0+row)*DDIM + kt + c4*4);
            *(uint4*)&Xs[row][c4*4] =
                make_uint4(f2tf(v.x), f2tf(v.y), f2tf(v.z), f2tf(v.w));
        }
        {
            int row = tid >> 2, c4 = tid & 3;
            float4 v = *(const float4*)(W + (size_t)(n0+row)*DDIM + kt + c4*4);
            Ws[c4*4+0][row]=f2tf(v.x); Ws[c4*4+1][row]=f2tf(v.y);
            Ws[c4*4+2][row]=f2tf(v.z); Ws[c4*4+3][row]=f2tf(v.w);
        }
        __syncthreads();

        #pragma unroll
        for (int ks=0; ks<2; ks++){
            const int kb = ks*8;
            uint32_t a[2][4], b[4][2];
            #pragma unroll
            for (int mt=0; mt<2; mt++){
                int r = wm*32 + mt*16;
                a[mt][0]=Xs[r+g  ][kb+tig  ];
                a[mt][1]=Xs[r+g+8][kb+tig  ];
                a[mt][2]=Xs[r+g  ][kb+tig+4];
                a[mt][3]=Xs[r+g+8][kb+tig+4];
            }
            #pragma unroll
            for (int nt=0; nt<4; nt++){
                int n = wn*32 + nt*8 + g;
                b[nt][0]=Ws[kb+tig  ][n];
                b[nt][1]=Ws[kb+tig+4][n];
            }
            #pragma unroll
            for (int mt=0;mt<2;mt++)
                #pragma unroll
                for (int nt=0;nt<4;nt++)
                    mma8(acc[mt][nt], a[mt], b[nt]);
        }
        __syncthreads();
    }

    const int h = n0 >> 6;
    #pragma unroll
    for (int mt=0;mt<2;mt++){
        #pragma unroll
        for (int half=0; half<2; half++){
            int m  = m0 + wm*32 + mt*16 + g + half*8;
            int b_ = m >> 11;
            int s  = m & (SS-1);
            float* orow = Out + (((size_t)(b_*HH + h))*SS + s)*DH;
            #pragma unroll
            for (int nt=0; nt<4; nt++){
                int d = wn*32 + nt*8 + tig*2;
                float2 v;
                v.x = acc[mt][nt][half*2+0];
                v.y = acc[mt][nt][half*2+1];
                *(float2*)(orow + d) = v;
            }
        }
    }
}

// ============================================================================
// Flash attention v2: one CTA per (qblock=128, h, b). 4 warps, M=32/warp
// (two 16-row tiles) -> B fragments shared across M-tiles: 1.25 LDS/MMA.
// Dynamic smem: Ks[64][68] | Vt[64][68] | Pb[128][68]  (= 69632 B).
// Pad 68 == 4 mod 32 -> all fragment accesses conflict-free (bank = 4g+tig).
// P has its own buffer (warp-private rows) -> no mid-loop block barrier.
// R7 fix: Q staging covers FULL 64-float rows (16 float4/row, i<16).
// ============================================================================
#define AT_PAD 68
#define KS_OFF 0
#define VT_OFF (64*AT_PAD)
#define PB_OFF (128*AT_PAD)
#define AT_SMEM_WORDS (PB_OFF + 128*AT_PAD)
#define AT_SMEM_BYTES (AT_SMEM_WORDS*4)

__global__ __launch_bounds__(128) void attn_kernel(float* __restrict__ out){
    extern __shared__ uint32_t sm[];
    uint32_t* Ks = sm + KS_OFF;     // [64][68]  K tile [s][k]
    uint32_t* Vt = sm + VT_OFF;     // [64][68]  V tile transposed [d][s]
    uint32_t* Pb = sm + PB_OFF;     // [128][68] Q staging, then P tile

    const int tid = threadIdx.x;
    const int w   = tid >> 5, lane = tid & 31;
    const int g   = lane >> 2, tig = lane & 3;
    const int q0  = blockIdx.x * 128;
    const int h   = blockIdx.y, b = blockIdx.z;
    const size_t headoff = ((size_t)(b*HH + h))*SS*DH;
    const float* Qg = g_Qh + headoff + (size_t)q0*DH;
    const float* Kg = g_Kh + headoff;
    const float* Vg = g_Vh + headoff;
    const float L2E = 1.44269504088896340736f;
    const float NEG_INF = __int_as_float(0xff800000);

    // ---- Stage Q (scaled by 0.125) into Pb: 2048 float4 = 128 rows x 16
    #pragma unroll
    for (int i=0;i<16;i++){
        int idx = tid + i*128;
        int row = idx >> 4, c4 = idx & 15;
        float4 v = *(const float4*)(Qg + (size_t)row*DH + c4*4);
        *(uint4*)&Pb[row*AT_PAD + c4*4] =
            make_uint4(f2tf(v.x*0.125f), f2tf(v.y*0.125f),
                       f2tf(v.z*0.125f), f2tf(v.w*0.125f));
    }
    __syncthreads();
    uint32_t qa[2][8][4];
    #pragma unroll
    for (int mt=0; mt<2; mt++){
        const int r = w*32 + mt*16;
        #pragma unroll
        for (int ks=0; ks<8; ks++){
            int kb = ks*8;
            qa[mt][ks][0]=Pb[(r+g  )*AT_PAD + kb+tig  ];
            qa[mt][ks][1]=Pb[(r+g+8)*AT_PAD + kb+tig  ];
            qa[mt][ks][2]=Pb[(r+g  )*AT_PAD + kb+tig+4];
            qa[mt][ks][3]=Pb[(r+g+8)*AT_PAD + kb+tig+4];
        }
    }

    float Oacc[2][8][4];
    #pragma unroll
    for (int mt=0;mt<2;mt++)
        #pragma unroll
        for (int nt=0;nt<8;nt++)
            #pragma unroll
            for (int c=0;c<4;c++) Oacc[mt][nt][c]=0.f;
    float mr[2][2] = {{NEG_INF,NEG_INF},{NEG_INF,NEG_INF}};
    float lr[2][2] = {{0.f,0.f},{0.f,0.f}};

    for (int t0 = 0; t0 < SS; t0 += 64){
        __syncthreads();   // prev QK done with Ks, prev PV done with Vt
        // ---- Stage K [s][k] and V transposed [d][s]
        #pragma unroll
        for (int i=0;i<8;i++){
            int idx = tid + i*128;
            int row = idx >> 4, c4 = idx & 15;
            float4 kv = *(const float4*)(Kg + (size_t)(t0+row)*DH + c4*4);
            *(uint4*)&Ks[row*AT_PAD + c4*4] =
                make_uint4(f2tf(kv.x), f2tf(kv.y), f2tf(kv.z), f2tf(kv.w));
            int vrow = idx & 63;
            int vc4  = idx >> 6;
            float4 vv = *(const float4*)(Vg + (size_t)(t0+vrow)*DH + vc4*4);
            Vt[(vc4*4+0)*AT_PAD + vrow]=f2tf(vv.x);
            Vt[(vc4*4+1)*AT_PAD + vrow]=f2tf(vv.y);
            Vt[(vc4*4+2)*AT_PAD + vrow]=f2tf(vv.z);
            Vt[(vc4*4+3)*AT_PAD + vrow]=f2tf(vv.w);
        }
        __syncthreads();

        // ---- S = Q K^T : both M-tiles share each B fragment
        float S[2][8][4];
        #pragma unroll
        for (int mt=0;mt<2;mt++)
            #pragma unroll
            for (int nt=0;nt<8;nt++)
                #pragma unroll
                for (int c=0;c<4;c++) S[mt][nt][c]=0.f;
        #pragma unroll
        for (int ks=0; ks<8; ks++){
            const int kb = ks*8;
            #pragma unroll
            for (int nt=0; nt<8; nt++){
                uint32_t bfr[2];
                bfr[0]=Ks[(nt*8+g)*AT_PAD + kb+tig  ];
                bfr[1]=Ks[(nt*8+g)*AT_PAD + kb+tig+4];
                mma8(S[0][nt], qa[0][ks], bfr);
                mma8(S[1][nt], qa[1][ks], bfr);
            }
        }

        // ---- Online softmax per M-tile, then write P (warp-private rows)
        #pragma unroll
        for (int mt=0; mt<2; mt++){
            float rmax0 = NEG_INF, rmax1 = NEG_INF;
            #pragma unroll
            for (int nt=0;nt<8;nt++){
                rmax0 = fmaxf(rmax0, fmaxf(S[mt][nt][0], S[mt][nt][1]));
                rmax1 = fmaxf(rmax1, fmaxf(S[mt][nt][2], S[mt][nt][3]));
            }
            rmax0 = fmaxf(rmax0, __shfl_xor_sync(0xffffffffu, rmax0, 1));
            rmax0 = fmaxf(rmax0, __shfl_xor_sync(0xffffffffu, rmax0, 2));
            rmax1 = fmaxf(rmax1, __shfl_xor_sync(0xffffffffu, rmax1, 1));
            rmax1 = fmaxf(rmax1, __shfl_xor_sync(0xffffffffu, rmax1, 2));
            float mn0 = fmaxf(mr[mt][0], rmax0), mn1 = fmaxf(mr[mt][1], rmax1);
            float al0 = ex2f((mr[mt][0] - mn0)*L2E);
            float al1 = ex2f((mr[mt][1] - mn1)*L2E);
            mr[mt][0] = mn0; mr[mt][1] = mn1;

            float rs0 = 0.f, rs1 = 0.f;
            #pragma unroll
            for (int nt=0;nt<8;nt++){
                S[mt][nt][0] = ex2f((S[mt][nt][0]-mn0)*L2E); rs0 += S[mt][nt][0];
                S[mt][nt][1] = ex2f((S[mt][nt][1]-mn0)*L2E); rs0 += S[mt][nt][1];
                S[mt][nt][2] = ex2f((S[mt][nt][2]-mn1)*L2E); rs1 += S[mt][nt][2];
                S[mt][nt][3] = ex2f((S[mt][nt][3]-mn1)*L2E); rs1 += S[mt][nt][3];
            }
            rs0 += __shfl_xor_sync(0xffffffffu, rs0, 1);
            rs0 += __shfl_xor_sync(0xffffffffu, rs0, 2);
            rs1 += __shfl_xor_sync(0xffffffffu, rs1, 1);
            rs1 += __shfl_xor_sync(0xffffffffu, rs1, 2);
            lr[mt][0] = lr[mt][0]*al0 + rs0;
            lr[mt][1] = lr[mt][1]*al1 + rs1;
            #pragma unroll
            for (int nt=0;nt<8;nt++){
                Oacc[mt][nt][0]*=al0; Oacc[mt][nt][1]*=al0;
                Oacc[mt][nt][2]*=al1; Oacc[mt][nt][3]*=al1;
            }

            // P write: STS.64 pairs into this warp's rows of Pb
            const int r = w*32 + mt*16;
            #pragma unroll
            for (int nt=0;nt<8;nt++){
                int c0 = nt*8 + tig*2;
                *(uint2*)&Pb[(r+g  )*AT_PAD + c0] =
                    make_uint2(f2tf(S[mt][nt][0]), f2tf(S[mt][nt][1]));
                *(uint2*)&Pb[(r+g+8)*AT_PAD + c0] =
                    make_uint2(f2tf(S[mt][nt][2]), f2tf(S[mt][nt][3]));
            }
        }
        __syncwarp();

        // ---- O += P V : both M-tiles share each bv fragment
        #pragma unroll
        for (int ks=0; ks<8; ks++){
            const int kb = ks*8;
            uint32_t pa[2][4];
            #pragma unroll
            for (int mt=0; mt<2; mt++){
                const int r = w*32 + mt*16;
                pa[mt][0]=Pb[(r+g  )*AT_PAD + kb+tig  ];
                pa[mt][1]=Pb[(r+g+8)*AT_PAD + kb+tig  ];
                pa[mt][2]=Pb[(r+g  )*AT_PAD + kb+tig+4];
                pa[mt][3]=Pb[(r+g+8)*AT_PAD + kb+tig+4];
            }
            #pragma unroll
            for (int nt=0; nt<8; nt++){
                uint32_t bv[2];
                bv[0]=Vt[(nt*8+g)*AT_PAD + kb+tig  ];
                bv[1]=Vt[(nt*8+g)*AT_PAD + kb+tig+4];
                mma8(Oacc[0][nt], pa[0], bv);
                mma8(Oacc[1][nt], pa[1], bv);
            }
        }
    }

    // ---- Epilogue: out[b, s, h*64+d] = O / l
    #pragma unroll
    for (int mt=0; mt<2; mt++){
        float inv0 = 1.f / lr[mt][0], inv1 = 1.f / lr[mt][1];
        int s0 = q0 + w*32 + mt*16 + g;
        #pragma unroll
        for (int nt=0;nt<8;nt++){
            int d = nt*8 + tig*2;
            float2 v0; v0.x = Oacc[mt][nt][0]*inv0; v0.y = Oacc[mt][nt][1]*inv0;
            *(float2*)(out + ((size_t)b*SS + s0  )*DDIM + h*DH + d) = v0;
            float2 v1; v1.x = Oacc[mt][nt][2]*inv1; v1.y = Oacc[mt][nt][3]*inv1;
            *(float2*)(out + ((size_t)b*SS + s0+8)*DDIM + h*DH + d) = v1;
        }
    }
}

extern "C" void kernel_launch(void* const* d_in, const int* in_sizes, int n_in,
                              void* d_out, int out_size){
    const float* q  = (const float*)d_in[0];
    const float* k  = (const float*)d_in[1];
    const float* v  = (const float*)d_in[2];
    const float* Wq = (const float*)d_in[3];
    const float* Wk = (const float*)d_in[4];
    const float* Wv = (const float*)d_in[5];

    dim3 pg(DDIM/64, MM/128, 3);   // fused Q/K/V projections
    proj_kernel<<<pg, 256>>>(q, k, v, Wq, Wk, Wv);

    cudaFuncSetAttribute(attn_kernel,
                         cudaFuncAttributeMaxDynamicSharedMemorySize,
                         AT_SMEM_BYTES);
    dim3 ag(SS/128, HH, BB);       // (16, 16, 4)
    attn_kernel<<<ag, 128, AT_SMEM_BYTES>>>((float*)d_out);
}

// round 9
// speedup vs baseline: 1.8144x; 1.0404x over previous
#include <cuda_runtime.h>
#include <cuda_bf16.h>
#include <cstdint>

#define BB 4
#define SS 2048
#define DDIM 1024
#define HH 16
#define DH 64
#define MM (BB*SS)

// Head-major scratch [B,H,S,Dh] fp32 (allocation-free: __device__ globals)
__device__ float g_Qh[(size_t)BB*HH*SS*DH];
__device__ float g_Kh[(size_t)BB*HH*SS*DH];
__device__ float g_Vh[(size_t)BB*HH*SS*DH];

__device__ __forceinline__ uint32_t f2tf(float x){
    uint32_t y; asm("cvt.rna.tf32.f32 %0, %1;" : "=r"(y) : "f"(x)); return y;
}
__device__ __forceinline__ float ex2f(float x){
    float y; asm("ex2.approx.ftz.f32 %0, %1;" : "=f"(y) : "f"(x)); return y;
}
__device__ __forceinline__ void mma8(float* d, const uint32_t* a, const uint32_t* b){
    asm volatile(
        "mma.sync.aligned.m16n8k8.row.col.f32.tf32.tf32.f32 "
        "{%0,%1,%2,%3},{%4,%5,%6,%7},{%8,%9},{%0,%1,%2,%3};\n"
        : "+f"(d[0]), "+f"(d[1]), "+f"(d[2]), "+f"(d[3])
        : "r"(a[0]), "r"(a[1]), "r"(a[2]), "r"(a[3]), "r"(b[0]), "r"(b[1]));
}

// ============================================================================
// Projection v2: Out[b,h,s,d] = sum_k X[m,k] * W[n,k]
// CTA tile 128x128 (TWO heads), BK=16, 8 warps (wm 4 x wn 2), warp tile 32x64.
// W stored ROW-MAJOR Ws[n][k] pad 20 -> B-frag bank (20g+tig): lane bijection,
// conflict-free (same layout as attn's K tile). 1.5 LDS/MMA (was 3.0).
// blockIdx.z selects which projection (0=Q, 1=K, 2=V).
// ============================================================================
__global__ __launch_bounds__(256) void proj_kernel(const float* __restrict__ Xq,
                                                   const float* __restrict__ Xk,
                                                   const float* __restrict__ Xv,
                                                   const float* __restrict__ Wq,
                                                   const float* __restrict__ Wk,
                                                   const float* __restrict__ Wv){
    __shared__ uint32_t Xs[128][20];
    __shared__ uint32_t Ws[128][20];

    const int which = blockIdx.z;
    const float* X = (which == 0) ? Xq : (which == 1) ? Xk : Xv;
    const float* W = (which == 0) ? Wq : (which == 1) ? Wk : Wv;
    float* Out     = (which == 0) ? g_Qh : (which == 1) ? g_Kh : g_Vh;

    const int tid  = threadIdx.x;
    const int wid  = tid >> 5, lane = tid & 31;
    const int g    = lane >> 2, tig = lane & 3;
    const int wm   = wid & 3,  wn  = wid >> 2;
    const int m0   = blockIdx.y * 128;
    const int n0   = blockIdx.x * 128;

    float acc[2][8][4];
    #pragma unroll
    for (int i=0;i<2;i++)
        #pragma unroll
        for (int j=0;j<8;j++)
            #pragma unroll
            for (int c=0;c<4;c++) acc[i][j][c]=0.f;

    for (int kt = 0; kt < DDIM; kt += 16){
        // X tile 128x16 and W tile 128x16 (each 512 float4, 2 per thread)
        #pragma unroll
        for (int i=0;i<2;i++){
            int idx = tid + i*256;
            int row = idx >> 2, c4 = idx & 3;
            float4 v = *(const float4*)(X + (size_t)(m0+row)*DDIM + kt + c4*4);
            *(uint4*)&Xs[row][c4*4] =
                make_uint4(f2tf(v.x), f2tf(v.y), f2tf(v.z), f2tf(v.w));
            float4 u = *(const float4*)(W + (size_t)(n0+row)*DDIM + kt + c4*4);
            *(uint4*)&Ws[row][c4*4] =
                make_uint4(f2tf(u.x), f2tf(u.y), f2tf(u.z), f2tf(u.w));
        }
        __syncthreads();

        #pragma unroll
        for (int ks=0; ks<2; ks++){
            const int kb = ks*8;
            uint32_t a[2][4], b[8][2];
            #pragma unroll
            for (int mt=0; mt<2; mt++){
                int r = wm*32 + mt*16;
                a[mt][0]=Xs[r+g  ][kb+tig  ];
                a[mt][1]=Xs[r+g+8][kb+tig  ];
                a[mt][2]=Xs[r+g  ][kb+tig+4];
                a[mt][3]=Xs[r+g+8][kb+tig+4];
            }
            #pragma unroll
            for (int nt=0; nt<8; nt++){
                int n = wn*64 + nt*8 + g;
                b[nt][0]=Ws[n][kb+tig  ];
                b[nt][1]=Ws[n][kb+tig+4];
            }
            #pragma unroll
            for (int mt=0;mt<2;mt++)
                #pragma unroll
                for (int nt=0;nt<8;nt++)
                    mma8(acc[mt][nt], a[mt], b[nt]);
        }
        __syncthreads();
    }

    // Epilogue: head-major store. Warp's 64-col span = one head: h = 2*bx + wn.
    const int h = (n0 >> 6) + wn;
    #pragma unroll
    for (int mt=0;mt<2;mt++){
        #pragma unroll
        for (int half=0; half<2; half++){
            int m  = m0 + wm*32 + mt*16 + g + half*8;
            int b_ = m >> 11;             // m / 2048
            int s  = m & (SS-1);
            float* orow = Out + (((size_t)(b_*HH + h))*SS + s)*DH;
            #pragma unroll
            for (int nt=0; nt<8; nt++){
                int d = nt*8 + tig*2;     // local d within head
                float2 v;
                v.x = acc[mt][nt][half*2+0];
                v.y = acc[mt][nt][half*2+1];
                *(float2*)(orow + d) = v;
            }
        }
    }
}

// ============================================================================
// Flash attention v2 (unchanged from R8 pass): one CTA per (qblock=128, h, b).
// 4 warps, M=32/warp, B fragments shared across M-tiles: 1.25 LDS/MMA.
// Dynamic smem: Ks[64][68] | Vt[64][68] | Pb[128][68]  (= 69632 B).
// ============================================================================
#define AT_PAD 68
#define KS_OFF 0
#define VT_OFF (64*AT_PAD)
#define PB_OFF (128*AT_PAD)
#define AT_SMEM_WORDS (PB_OFF + 128*AT_PAD)
#define AT_SMEM_BYTES (AT_SMEM_WORDS*4)

__global__ __launch_bounds__(128) void attn_kernel(float* __restrict__ out){
    extern __shared__ uint32_t sm[];
    uint32_t* Ks = sm + KS_OFF;     // [64][68]  K tile [s][k]
    uint32_t* Vt = sm + VT_OFF;     // [64][68]  V tile transposed [d][s]
    uint32_t* Pb = sm + PB_OFF;     // [128][68] Q staging, then P tile

    const int tid = threadIdx.x;
    const int w   = tid >> 5, lane = tid & 31;
    const int g   = lane >> 2, tig = lane & 3;
    const int q0  = blockIdx.x * 128;
    const int h   = blockIdx.y, b = blockIdx.z;
    const size_t headoff = ((size_t)(b*HH + h))*SS*DH;
    const float* Qg = g_Qh + headoff + (size_t)q0*DH;
    const float* Kg = g_Kh + headoff;
    const float* Vg = g_Vh + headoff;
    const float L2E = 1.44269504088896340736f;
    const float NEG_INF = __int_as_float(0xff800000);

    // ---- Stage Q (scaled by 0.125) into Pb: 2048 float4 = 128 rows x 16
    #pragma unroll
    for (int i=0;i<16;i++){
        int idx = tid + i*128;
        int row = idx >> 4, c4 = idx & 15;
        float4 v = *(const float4*)(Qg + (size_t)row*DH + c4*4);
        *(uint4*)&Pb[row*AT_PAD + c4*4] =
            make_uint4(f2tf(v.x*0.125f), f2tf(v.y*0.125f),
                       f2tf(v.z*0.125f), f2tf(v.w*0.125f));
    }
    __syncthreads();
    uint32_t qa[2][8][4];
    #pragma unroll
    for (int mt=0; mt<2; mt++){
        const int r = w*32 + mt*16;
        #pragma unroll
        for (int ks=0; ks<8; ks++){
            int kb = ks*8;
            qa[mt][ks][0]=Pb[(r+g  )*AT_PAD + kb+tig  ];
            qa[mt][ks][1]=Pb[(r+g+8)*AT_PAD + kb+tig  ];
            qa[mt][ks][2]=Pb[(r+g  )*AT_PAD + kb+tig+4];
            qa[mt][ks][3]=Pb[(r+g+8)*AT_PAD + kb+tig+4];
        }
    }

    float Oacc[2][8][4];
    #pragma unroll
    for (int mt=0;mt<2;mt++)
        #pragma unroll
        for (int nt=0;nt<8;nt++)
            #pragma unroll
            for (int c=0;c<4;c++) Oacc[mt][nt][c]=0.f;
    float mr[2][2] = {{NEG_INF,NEG_INF},{NEG_INF,NEG_INF}};
    float lr[2][2] = {{0.f,0.f},{0.f,0.f}};

    for (int t0 = 0; t0 < SS; t0 += 64){
        __syncthreads();   // prev QK done with Ks, prev PV done with Vt
        // ---- Stage K [s][k] and V transposed [d][s]
        #pragma unroll
        for (int i=0;i<8;i++){
            int idx = tid + i*128;
            int row = idx >> 4, c4 = idx & 15;
            float4 kv = *(const float4*)(Kg + (size_t)(t0+row)*DH + c4*4);
            *(uint4*)&Ks[row*AT_PAD + c4*4] =
                make_uint4(f2tf(kv.x), f2tf(kv.y), f2tf(kv.z), f2tf(kv.w));
            int vrow = idx & 63;
            int vc4  = idx >> 6;
            float4 vv = *(const float4*)(Vg + (size_t)(t0+vrow)*DH + vc4*4);
            Vt[(vc4*4+0)*AT_PAD + vrow]=f2tf(vv.x);
            Vt[(vc4*4+1)*AT_PAD + vrow]=f2tf(vv.y);
            Vt[(vc4*4+2)*AT_PAD + vrow]=f2tf(vv.z);
            Vt[(vc4*4+3)*AT_PAD + vrow]=f2tf(vv.w);
        }
        __syncthreads();

        // ---- S = Q K^T : both M-tiles share each B fragment
        float S[2][8][4];
        #pragma unroll
        for (int mt=0;mt<2;mt++)
            #pragma unroll
            for (int nt=0;nt<8;nt++)
                #pragma unroll
                for (int c=0;c<4;c++) S[mt][nt][c]=0.f;
        #pragma unroll
        for (int ks=0; ks<8; ks++){
            const int kb = ks*8;
            #pragma unroll
            for (int nt=0; nt<8; nt++){
                uint32_t bfr[2];
                bfr[0]=Ks[(nt*8+g)*AT_PAD + kb+tig  ];
                bfr[1]=Ks[(nt*8+g)*AT_PAD + kb+tig+4];
                mma8(S[0][nt], qa[0][ks], bfr);
                mma8(S[1][nt], qa[1][ks], bfr);
            }
        }

        // ---- Online softmax per M-tile, then write P (warp-private rows)
        #pragma unroll
        for (int mt=0; mt<2; mt++){
            float rmax0 = NEG_INF, rmax1 = NEG_INF;
            #pragma unroll
            for (int nt=0;nt<8;nt++){
                rmax0 = fmaxf(rmax0, fmaxf(S[mt][nt][0], S[mt][nt][1]));
                rmax1 = fmaxf(rmax1, fmaxf(S[mt][nt][2], S[mt][nt][3]));
            }
            rmax0 = fmaxf(rmax0, __shfl_xor_sync(0xffffffffu, rmax0, 1));
            rmax0 = fmaxf(rmax0, __shfl_xor_sync(0xffffffffu, rmax0, 2));
            rmax1 = fmaxf(rmax1, __shfl_xor_sync(0xffffffffu, rmax1, 1));
            rmax1 = fmaxf(rmax1, __shfl_xor_sync(0xffffffffu, rmax1, 2));
            float mn0 = fmaxf(mr[mt][0], rmax0), mn1 = fmaxf(mr[mt][1], rmax1);
            float al0 = ex2f((mr[mt][0] - mn0)*L2E);
            float al1 = ex2f((mr[mt][1] - mn1)*L2E);
            mr[mt][0] = mn0; mr[mt][1] = mn1;

            float rs0 = 0.f, rs1 = 0.f;
            #pragma unroll
            for (int nt=0;nt<8;nt++){
                S[mt][nt][0] = ex2f((S[mt][nt][0]-mn0)*L2E); rs0 += S[mt][nt][0];
                S[mt][nt][1] = ex2f((S[mt][nt][1]-mn0)*L2E); rs0 += S[mt][nt][1];
                S[mt][nt][2] = ex2f((S[mt][nt][2]-mn1)*L2E); rs1 += S[mt][nt][2];
                S[mt][nt][3] = ex2f((S[mt][nt][3]-mn1)*L2E); rs1 += S[mt][nt][3];
            }
            rs0 += __shfl_xor_sync(0xffffffffu, rs0, 1);
            rs0 += __shfl_xor_sync(0xffffffffu, rs0, 2);
            rs1 += __shfl_xor_sync(0xffffffffu, rs1, 1);
            rs1 += __shfl_xor_sync(0xffffffffu, rs1, 2);
            lr[mt][0] = lr[mt][0]*al0 + rs0;
            lr[mt][1] = lr[mt][1]*al1 + rs1;
            #pragma unroll
            for (int nt=0;nt<8;nt++){
                Oacc[mt][nt][0]*=al0; Oacc[mt][nt][1]*=al0;
                Oacc[mt][nt][2]*=al1; Oacc[mt][nt][3]*=al1;
            }

            // P write: STS.64 pairs into this warp's rows of Pb
            const int r = w*32 + mt*16;
            #pragma unroll
            for (int nt=0;nt<8;nt++){
                int c0 = nt*8 + tig*2;
                *(uint2*)&Pb[(r+g  )*AT_PAD + c0] =
                    make_uint2(f2tf(S[mt][nt][0]), f2tf(S[mt][nt][1]));
                *(uint2*)&Pb[(r+g+8)*AT_PAD + c0] =
                    make_uint2(f2tf(S[mt][nt][2]), f2tf(S[mt][nt][3]));
            }
        }
        __syncwarp();

        // ---- O += P V : both M-tiles share each bv fragment
        #pragma unroll
        for (int ks=0; ks<8; ks++){
            const int kb = ks*8;
            uint32_t pa[2][4];
            #pragma unroll
            for (int mt=0; mt<2; mt++){
                const int r = w*32 + mt*16;
                pa[mt][0]=Pb[(r+g  )*AT_PAD + kb+tig  ];
                pa[mt][1]=Pb[(r+g+8)*AT_PAD + kb+tig  ];
                pa[mt][2]=Pb[(r+g  )*AT_PAD + kb+tig+4];
                pa[mt][3]=Pb[(r+g+8)*AT_PAD + kb+tig+4];
            }
            #pragma unroll
            for (int nt=0; nt<8; nt++){
                uint32_t bv[2];
                bv[0]=Vt[(nt*8+g)*AT_PAD + kb+tig  ];
                bv[1]=Vt[(nt*8+g)*AT_PAD + kb+tig+4];
                mma8(Oacc[0][nt], pa[0], bv);
                mma8(Oacc[1][nt], pa[1], bv);
            }
        }
    }

    // ---- Epilogue: out[b, s, h*64+d] = O / l
    #pragma unroll
    for (int mt=0; mt<2; mt++){
        float inv0 = 1.f / lr[mt][0], inv1 = 1.f / lr[mt][1];
        int s0 = q0 + w*32 + mt*16 + g;
        #pragma unroll
        for (int nt=0;nt<8;nt++){
            int d = nt*8 + tig*2;
            float2 v0; v0.x = Oacc[mt][nt][0]*inv0; v0.y = Oacc[mt][nt][1]*inv0;
            *(float2*)(out + ((size_t)b*SS + s0  )*DDIM + h*DH + d) = v0;
            float2 v1; v1.x = Oacc[mt][nt][2]*inv1; v1.y = Oacc[mt][nt][3]*inv1;
            *(float2*)(out + ((size_t)b*SS + s0+8)*DDIM + h*DH + d) = v1;
        }
    }
}

extern "C" void kernel_launch(void* const* d_in, const int* in_sizes, int n_in,
                              void* d_out, int out_size){
    const float* q  = (const float*)d_in[0];
    const float* k  = (const float*)d_in[1];
    const float* v  = (const float*)d_in[2];
    const float* Wq = (const float*)d_in[3];
    const float* Wk = (const float*)d_in[4];
    const float* Wv = (const float*)d_in[5];

    dim3 pg(DDIM/128, MM/128, 3);  // (8, 64, 3) — fused Q/K/V projections
    proj_kernel<<<pg, 256>>>(q, k, v, Wq, Wk, Wv);

    cudaFuncSetAttribute(attn_kernel,
                         cudaFuncAttributeMaxDynamicSharedMemorySize,
                         AT_SMEM_BYTES);
    dim3 ag(SS/128, HH, BB);       // (16, 16, 4)
    attn_kernel<<<ag, 128, AT_SMEM_BYTES>>>((float*)d_out);
}

// round 10
// speedup vs baseline: 1.9846x; 1.0938x over previous
#include <cuda_runtime.h>
#include <cuda_bf16.h>
#include <cstdint>

#define BB 4
#define SS 2048
#define DDIM 1024
#define HH 16
#define DH 64
#define MM (BB*SS)

// Head-major scratch [B,H,S,Dh] fp32 (allocation-free: __device__ globals)
__device__ float g_Qh[(size_t)BB*HH*SS*DH];
__device__ float g_Kh[(size_t)BB*HH*SS*DH];
__device__ float g_Vh[(size_t)BB*HH*SS*DH];

__device__ __forceinline__ uint32_t f2tf(float x){
    uint32_t y; asm("cvt.rna.tf32.f32 %0, %1;" : "=r"(y) : "f"(x)); return y;
}
__device__ __forceinline__ float ex2f(float x){
    float y; asm("ex2.approx.ftz.f32 %0, %1;" : "=f"(y) : "f"(x)); return y;
}
__device__ __forceinline__ void mma8(float* d, const uint32_t* a, const uint32_t* b){
    asm volatile(
        "mma.sync.aligned.m16n8k8.row.col.f32.tf32.tf32.f32 "
        "{%0,%1,%2,%3},{%4,%5,%6,%7},{%8,%9},{%0,%1,%2,%3};\n"
        : "+f"(d[0]), "+f"(d[1]), "+f"(d[2]), "+f"(d[3])
        : "r"(a[0]), "r"(a[1]), "r"(a[2]), "r"(a[3]), "r"(b[0]), "r"(b[1]));
}

// ============================================================================
// Projection v3: Out[b,h,s,d] = sum_k X[m,k] * W[n,k]
// CTA tile 128x128 (two heads), BK=16, 8 warps, warp tile 32x64, 1.5 LDS/MMA.
// R10: DOUBLE-BUFFERED k-loop — prefetch tile k+1 into registers during the
// MMAs of tile k, STS into the alternate buffer, ONE barrier per iteration.
// __launch_bounds__(256,2) pins regs <=128 to keep 2 CTAs/SM.
// ============================================================================
__global__ __launch_bounds__(256, 2) void proj_kernel(const float* __restrict__ Xq,
                                                      const float* __restrict__ Xk,
                                                      const float* __restrict__ Xv,
                                                      const float* __restrict__ Wq,
                                                      const float* __restrict__ Wk,
                                                      const float* __restrict__ Wv){
    __shared__ uint32_t Xs[2][128][20];
    __shared__ uint32_t Ws[2][128][20];

    const int which = blockIdx.z;
    const float* X = (which == 0) ? Xq : (which == 1) ? Xk : Xv;
    const float* W = (which == 0) ? Wq : (which == 1) ? Wk : Wv;
    float* Out     = (which == 0) ? g_Qh : (which == 1) ? g_Kh : g_Vh;

    const int tid  = threadIdx.x;
    const int wid  = tid >> 5, lane = tid & 31;
    const int g    = lane >> 2, tig = lane & 3;
    const int wm   = wid & 3,  wn  = wid >> 2;
    const int m0   = blockIdx.y * 128;
    const int n0   = blockIdx.x * 128;

    // Per-thread fixed staging coordinates: idx = tid + i*256
    int srow[2], sc4[2];
    #pragma unroll
    for (int i=0;i<2;i++){
        int idx = tid + i*256;
        srow[i] = idx >> 2;
        sc4[i]  = idx & 3;
    }
    const float* Xrow0 = X + (size_t)(m0+srow[0])*DDIM + sc4[0]*4;
    const float* Xrow1 = X + (size_t)(m0+srow[1])*DDIM + sc4[1]*4;
    const float* Wrow0 = W + (size_t)(n0+srow[0])*DDIM + sc4[0]*4;
    const float* Wrow1 = W + (size_t)(n0+srow[1])*DDIM + sc4[1]*4;

    float acc[2][8][4];
    #pragma unroll
    for (int i=0;i<2;i++)
        #pragma unroll
        for (int j=0;j<8;j++)
            #pragma unroll
            for (int c=0;c<4;c++) acc[i][j][c]=0.f;

    // ---- Prologue: load k-tile 0, stage into buffer 0
    float4 xr0 = *(const float4*)(Xrow0);
    float4 xr1 = *(const float4*)(Xrow1);
    float4 wr0 = *(const float4*)(Wrow0);
    float4 wr1 = *(const float4*)(Wrow1);
    *(uint4*)&Xs[0][srow[0]][sc4[0]*4] = make_uint4(f2tf(xr0.x),f2tf(xr0.y),f2tf(xr0.z),f2tf(xr0.w));
    *(uint4*)&Xs[0][srow[1]][sc4[1]*4] = make_uint4(f2tf(xr1.x),f2tf(xr1.y),f2tf(xr1.z),f2tf(xr1.w));
    *(uint4*)&Ws[0][srow[0]][sc4[0]*4] = make_uint4(f2tf(wr0.x),f2tf(wr0.y),f2tf(wr0.z),f2tf(wr0.w));
    *(uint4*)&Ws[0][srow[1]][sc4[1]*4] = make_uint4(f2tf(wr1.x),f2tf(wr1.y),f2tf(wr1.z),f2tf(wr1.w));
    __syncthreads();

    for (int t = 0; t < 64; t++){
        const int cur = t & 1;
        // ---- Prefetch next k-tile into registers (latency hidden by MMAs)
        if (t + 1 < 64){
            const int kt = (t + 1) * 16;
            xr0 = *(const float4*)(Xrow0 + kt);
            xr1 = *(const float4*)(Xrow1 + kt);
            wr0 = *(const float4*)(Wrow0 + kt);
            wr1 = *(const float4*)(Wrow1 + kt);
        }

        // ---- Compute on current buffer
        #pragma unroll
        for (int ks=0; ks<2; ks++){
            const int kb = ks*8;
            uint32_t a[2][4], b[8][2];
            #pragma unroll
            for (int mt=0; mt<2; mt++){
                int r = wm*32 + mt*16;
                a[mt][0]=Xs[cur][r+g  ][kb+tig  ];
                a[mt][1]=Xs[cur][r+g+8][kb+tig  ];
                a[mt][2]=Xs[cur][r+g  ][kb+tig+4];
                a[mt][3]=Xs[cur][r+g+8][kb+tig+4];
            }
            #pragma unroll
            for (int nt=0; nt<8; nt++){
                int n = wn*64 + nt*8 + g;
                b[nt][0]=Ws[cur][n][kb+tig  ];
                b[nt][1]=Ws[cur][n][kb+tig+4];
            }
            #pragma unroll
            for (int mt=0;mt<2;mt++)
                #pragma unroll
                for (int nt=0;nt<8;nt++)
                    mma8(acc[mt][nt], a[mt], b[nt]);
        }

        // ---- Stage next tile into the alternate buffer, one barrier per iter
        if (t + 1 < 64){
            const int nxt = cur ^ 1;
            *(uint4*)&Xs[nxt][srow[0]][sc4[0]*4] = make_uint4(f2tf(xr0.x),f2tf(xr0.y),f2tf(xr0.z),f2tf(xr0.w));
            *(uint4*)&Xs[nxt][srow[1]][sc4[1]*4] = make_uint4(f2tf(xr1.x),f2tf(xr1.y),f2tf(xr1.z),f2tf(xr1.w));
            *(uint4*)&Ws[nxt][srow[0]][sc4[0]*4] = make_uint4(f2tf(wr0.x),f2tf(wr0.y),f2tf(wr0.z),f2tf(wr0.w));
            *(uint4*)&Ws[nxt][srow[1]][sc4[1]*4] = make_uint4(f2tf(wr1.x),f2tf(wr1.y),f2tf(wr1.z),f2tf(wr1.w));
            __syncthreads();
        }
    }

    // Epilogue: head-major store. Warp's 64-col span = one head: h = 2*bx + wn.
    const int h = (n0 >> 6) + wn;
    #pragma unroll
    for (int mt=0;mt<2;mt++){
        #pragma unroll
        for (int half=0; half<2; half++){
            int m  = m0 + wm*32 + mt*16 + g + half*8;
            int b_ = m >> 11;             // m / 2048
            int s  = m & (SS-1);
            float* orow = Out + (((size_t)(b_*HH + h))*SS + s)*DH;
            #pragma unroll
            for (int nt=0; nt<8; nt++){
                int d = nt*8 + tig*2;     // local d within head
                float2 v;
                v.x = acc[mt][nt][half*2+0];
                v.y = acc[mt][nt][half*2+1];
                *(float2*)(orow + d) = v;
            }
        }
    }
}

// ============================================================================
// Flash attention v2 (unchanged from R8/R9 pass): one CTA per (qblock=128, h, b).
// 4 warps, M=32/warp, B fragments shared across M-tiles: 1.25 LDS/MMA.
// Dynamic smem: Ks[64][68] | Vt[64][68] | Pb[128][68]  (= 69632 B).
// ============================================================================
#define AT_PAD 68
#define KS_OFF 0
#define VT_OFF (64*AT_PAD)
#define PB_OFF (128*AT_PAD)
#define AT_SMEM_WORDS (PB_OFF + 128*AT_PAD)
#define AT_SMEM_BYTES (AT_SMEM_WORDS*4)

__global__ __launch_bounds__(128) void attn_kernel(float* __restrict__ out){
    extern __shared__ uint32_t sm[];
    uint32_t* Ks = sm + KS_OFF;     // [64][68]  K tile [s][k]
    uint32_t* Vt = sm + VT_OFF;     // [64][68]  V tile transposed [d][s]
    uint32_t* Pb = sm + PB_OFF;     // [128][68] Q staging, then P tile

    const int tid = threadIdx.x;
    const int w   = tid >> 5, lane = tid & 31;
    const int g   = lane >> 2, tig = lane & 3;
    const int q0  = blockIdx.x * 128;
    const int h   = blockIdx.y, b = blockIdx.z;
    const size_t headoff = ((size_t)(b*HH + h))*SS*DH;
    const float* Qg = g_Qh + headoff + (size_t)q0*DH;
    const float* Kg = g_Kh + headoff;
    const float* Vg = g_Vh + headoff;
    const float L2E = 1.44269504088896340736f;
    const float NEG_INF = __int_as_float(0xff800000);

    // ---- Stage Q (scaled by 0.125) into Pb: 2048 float4 = 128 rows x 16
    #pragma unroll
    for (int i=0;i<16;i++){
        int idx = tid + i*128;
        int row = idx >> 4, c4 = idx & 15;
        float4 v = *(const float4*)(Qg + (size_t)row*DH + c4*4);
        *(uint4*)&Pb[row*AT_PAD + c4*4] =
            make_uint4(f2tf(v.x*0.125f), f2tf(v.y*0.125f),
                       f2tf(v.z*0.125f), f2tf(v.w*0.125f));
    }
    __syncthreads();
    uint32_t qa[2][8][4];
    #pragma unroll
    for (int mt=0; mt<2; mt++){
        const int r = w*32 + mt*16;
        #pragma unroll
        for (int ks=0; ks<8; ks++){
            int kb = ks*8;
            qa[mt][ks][0]=Pb[(r+g  )*AT_PAD + kb+tig  ];
            qa[mt][ks][1]=Pb[(r+g+8)*AT_PAD + kb+tig  ];
            qa[mt][ks][2]=Pb[(r+g  )*AT_PAD + kb+tig+4];
            qa[mt][ks][3]=Pb[(r+g+8)*AT_PAD + kb+tig+4];
        }
    }

    float Oacc[2][8][4];
    #pragma unroll
    for (int mt=0;mt<2;mt++)
        #pragma unroll
        for (int nt=0;nt<8;nt++)
            #pragma unroll
            for (int c=0;c<4;c++) Oacc[mt][nt][c]=0.f;
    float mr[2][2] = {{NEG_INF,NEG_INF},{NEG_INF,NEG_INF}};
    float lr[2][2] = {{0.f,0.f},{0.f,0.f}};

    for (int t0 = 0; t0 < SS; t0 += 64){
        __syncthreads();   // prev QK done with Ks, prev PV done with Vt
        // ---- Stage K [s][k] and V transposed [d][s]
        #pragma unroll
        for (int i=0;i<8;i++){
            int idx = tid + i*128;
            int row = idx >> 4, c4 = idx & 15;
            float4 kv = *(const float4*)(Kg + (size_t)(t0+row)*DH + c4*4);
            *(uint4*)&Ks[row*AT_PAD + c4*4] =
                make_uint4(f2tf(kv.x), f2tf(kv.y), f2tf(kv.z), f2tf(kv.w));
            int vrow = idx & 63;
            int vc4  = idx >> 6;
            float4 vv = *(const float4*)(Vg + (size_t)(t0+vrow)*DH + vc4*4);
            Vt[(vc4*4+0)*AT_PAD + vrow]=f2tf(vv.x);
            Vt[(vc4*4+1)*AT_PAD + vrow]=f2tf(vv.y);
            Vt[(vc4*4+2)*AT_PAD + vrow]=f2tf(vv.z);
            Vt[(vc4*4+3)*AT_PAD + vrow]=f2tf(vv.w);
        }
        __syncthreads();

        // ---- S = Q K^T : both M-tiles share each B fragment
        float S[2][8][4];
        #pragma unroll
        for (int mt=0;mt<2;mt++)
            #pragma unroll
            for (int nt=0;nt<8;nt++)
                #pragma unroll
                for (int c=0;c<4;c++) S[mt][nt][c]=0.f;
        #pragma unroll
        for (int ks=0; ks<8; ks++){
            const int kb = ks*8;
            #pragma unroll
            for (int nt=0; nt<8; nt++){
                uint32_t bfr[2];
                bfr[0]=Ks[(nt*8+g)*AT_PAD + kb+tig  ];
                bfr[1]=Ks[(nt*8+g)*AT_PAD + kb+tig+4];
                mma8(S[0][nt], qa[0][ks], bfr);
                mma8(S[1][nt], qa[1][ks], bfr);
            }
        }

        // ---- Online softmax per M-tile, then write P (warp-private rows)
        #pragma unroll
        for (int mt=0; mt<2; mt++){
            float rmax0 = NEG_INF, rmax1 = NEG_INF;
            #pragma unroll
            for (int nt=0;nt<8;nt++){
                rmax0 = fmaxf(rmax0, fmaxf(S[mt][nt][0], S[mt][nt][1]));
                rmax1 = fmaxf(rmax1, fmaxf(S[mt][nt][2], S[mt][nt][3]));
            }
            rmax0 = fmaxf(rmax0, __shfl_xor_sync(0xffffffffu, rmax0, 1));
            rmax0 = fmaxf(rmax0, __shfl_xor_sync(0xffffffffu, rmax0, 2));
            rmax1 = fmaxf(rmax1, __shfl_xor_sync(0xffffffffu, rmax1, 1));
            rmax1 = fmaxf(rmax1, __shfl_xor_sync(0xffffffffu, rmax1, 2));
            float mn0 = fmaxf(mr[mt][0], rmax0), mn1 = fmaxf(mr[mt][1], rmax1);
            float al0 = ex2f((mr[mt][0] - mn0)*L2E);
            float al1 = ex2f((mr[mt][1] - mn1)*L2E);
            mr[mt][0] = mn0; mr[mt][1] = mn1;

            float rs0 = 0.f, rs1 = 0.f;
            #pragma unroll
            for (int nt=0;nt<8;nt++){
                S[mt][nt][0] = ex2f((S[mt][nt][0]-mn0)*L2E); rs0 += S[mt][nt][0];
                S[mt][nt][1] = ex2f((S[mt][nt][1]-mn0)*L2E); rs0 += S[mt][nt][1];
                S[mt][nt][2] = ex2f((S[mt][nt][2]-mn1)*L2E); rs1 += S[mt][nt][2];
                S[mt][nt][3] = ex2f((S[mt][nt][3]-mn1)*L2E); rs1 += S[mt][nt][3];
            }
            rs0 += __shfl_xor_sync(0xffffffffu, rs0, 1);
            rs0 += __shfl_xor_sync(0xffffffffu, rs0, 2);
            rs1 += __shfl_xor_sync(0xffffffffu, rs1, 1);
            rs1 += __shfl_xor_sync(0xffffffffu, rs1, 2);
            lr[mt][0] = lr[mt][0]*al0 + rs0;
            lr[mt][1] = lr[mt][1]*al1 + rs1;
            #pragma unroll
            for (int nt=0;nt<8;nt++){
                Oacc[mt][nt][0]*=al0; Oacc[mt][nt][1]*=al0;
                Oacc[mt][nt][2]*=al1; Oacc[mt][nt][3]*=al1;
            }

            // P write: STS.64 pairs into this warp's rows of Pb
            const int r = w*32 + mt*16;
            #pragma unroll
            for (int nt=0;nt<8;nt++){
                int c0 = nt*8 + tig*2;
                *(uint2*)&Pb[(r+g  )*AT_PAD + c0] =
                    make_uint2(f2tf(S[mt][nt][0]), f2tf(S[mt][nt][1]));
                *(uint2*)&Pb[(r+g+8)*AT_PAD + c0] =
                    make_uint2(f2tf(S[mt][nt][2]), f2tf(S[mt][nt][3]));
            }
        }
        __syncwarp();

        // ---- O += P V : both M-tiles share each bv fragment
        #pragma unroll
        for (int ks=0; ks<8; ks++){
            const int kb = ks*8;
            uint32_t pa[2][4];
            #pragma unroll
            for (int mt=0; mt<2; mt++){
                const int r = w*32 + mt*16;
                pa[mt][0]=Pb[(r+g  )*AT_PAD + kb+tig  ];
                pa[mt][1]=Pb[(r+g+8)*AT_PAD + kb+tig  ];
                pa[mt][2]=Pb[(r+g  )*AT_PAD + kb+tig+4];
                pa[mt][3]=Pb[(r+g+8)*AT_PAD + kb+tig+4];
            }
            #pragma unroll
            for (int nt=0; nt<8; nt++){
                uint32_t bv[2];
                bv[0]=Vt[(nt*8+g)*AT_PAD + kb+tig  ];
                bv[1]=Vt[(nt*8+g)*AT_PAD + kb+tig+4];
                mma8(Oacc[0][nt], pa[0], bv);
                mma8(Oacc[1][nt], pa[1], bv);
            }
        }
    }

    // ---- Epilogue: out[b, s, h*64+d] = O / l
    #pragma unroll
    for (int mt=0; mt<2; mt++){
        float inv0 = 1.f / lr[mt][0], inv1 = 1.f / lr[mt][1];
        int s0 = q0 + w*32 + mt*16 + g;
        #pragma unroll
        for (int nt=0;nt<8;nt++){
            int d = nt*8 + tig*2;
            float2 v0; v0.x = Oacc[mt][nt][0]*inv0; v0.y = Oacc[mt][nt][1]*inv0;
            *(float2*)(out + ((size_t)b*SS + s0  )*DDIM + h*DH + d) = v0;
            float2 v1; v1.x = Oacc[mt][nt][2]*inv1; v1.y = Oacc[mt][nt][3]*inv1;
            *(float2*)(out + ((size_t)b*SS + s0+8)*DDIM + h*DH + d) = v1;
        }
    }
}

extern "C" void kernel_launch(void* const* d_in, const int* in_sizes, int n_in,
                              void* d_out, int out_size){
    const float* q  = (const float*)d_in[0];
    const float* k  = (const float*)d_in[1];
    const float* v  = (const float*)d_in[2];
    const float* Wq = (const float*)d_in[3];
    const float* Wk = (const float*)d_in[4];
    const float* Wv = (const float*)d_in[5];

    dim3 pg(DDIM/128, MM/128, 3);  // (8, 64, 3) — fused Q/K/V projections
    proj_kernel<<<pg, 256>>>(q, k, v, Wq, Wk, Wv);

    cudaFuncSetAttribute(attn_kernel,
                         cudaFuncAttributeMaxDynamicSharedMemorySize,
                         AT_SMEM_BYTES);
    dim3 ag(SS/128, HH, BB);       // (16, 16, 4)
    attn_kernel<<<ag, 128, AT_SMEM_BYTES>>>((float*)d_out);
}

// round 11
// speedup vs baseline: 2.1727x; 1.0948x over previous
#include <cuda_runtime.h>
#include <cuda_bf16.h>
#include <cstdint>

#define BB 4
#define SS 2048
#define DDIM 1024
#define HH 16
#define DH 64
#define MM (BB*SS)

// Head-major scratch [B,H,S,Dh] fp32 (allocation-free: __device__ globals)
__device__ float g_Qh[(size_t)BB*HH*SS*DH];
__device__ float g_Kh[(size_t)BB*HH*SS*DH];
__device__ float g_Vh[(size_t)BB*HH*SS*DH];

__device__ __forceinline__ uint32_t f2tf(float x){
    uint32_t y; asm("cvt.rna.tf32.f32 %0, %1;" : "=r"(y) : "f"(x)); return y;
}
__device__ __forceinline__ float ex2f(float x){
    float y; asm("ex2.approx.ftz.f32 %0, %1;" : "=f"(y) : "f"(x)); return y;
}
__device__ __forceinline__ void mma8(float* d, const uint32_t* a, const uint32_t* b){
    asm volatile(
        "mma.sync.aligned.m16n8k8.row.col.f32.tf32.tf32.f32 "
        "{%0,%1,%2,%3},{%4,%5,%6,%7},{%8,%9},{%0,%1,%2,%3};\n"
        : "+f"(d[0]), "+f"(d[1]), "+f"(d[2]), "+f"(d[3])
        : "r"(a[0]), "r"(a[1]), "r"(a[2]), "r"(a[3]), "r"(b[0]), "r"(b[1]));
}
__device__ __forceinline__ void cpa16(uint32_t dst, const float* src){
    asm volatile("cp.async.ca.shared.global [%0], [%1], 16;" :: "r"(dst), "l"(src));
}
#define CP_COMMIT() asm volatile("cp.async.commit_group;" ::: "memory")
#define CP_WAIT0()  asm volatile("cp.async.wait_group 0;" ::: "memory")

// ============================================================================
// Projection v3 (unchanged from R10 pass): CTA tile 128x128, BK=16, 8 warps,
// double-buffered k-loop with register prefetch, one barrier per iteration.
// ============================================================================
__global__ __launch_bounds__(256, 2) void proj_kernel(const float* __restrict__ Xq,
                                                      const float* __restrict__ Xk,
                                                      const float* __restrict__ Xv,
                                                      const float* __restrict__ Wq,
                                                      const float* __restrict__ Wk,
                                                      const float* __restrict__ Wv){
    __shared__ uint32_t Xs[2][128][20];
    __shared__ uint32_t Ws[2][128][20];

    const int which = blockIdx.z;
    const float* X = (which == 0) ? Xq : (which == 1) ? Xk : Xv;
    const float* W = (which == 0) ? Wq : (which == 1) ? Wk : Wv;
    float* Out     = (which == 0) ? g_Qh : (which == 1) ? g_Kh : g_Vh;

    const int tid  = threadIdx.x;
    const int wid  = tid >> 5, lane = tid & 31;
    const int g    = lane >> 2, tig = lane & 3;
    const int wm   = wid & 3,  wn  = wid >> 2;
    const int m0   = blockIdx.y * 128;
    const int n0   = blockIdx.x * 128;

    int srow[2], sc4[2];
    #pragma unroll
    for (int i=0;i<2;i++){
        int idx = tid + i*256;
        srow[i] = idx >> 2;
        sc4[i]  = idx & 3;
    }
    const float* Xrow0 = X + (size_t)(m0+srow[0])*DDIM + sc4[0]*4;
    const float* Xrow1 = X + (size_t)(m0+srow[1])*DDIM + sc4[1]*4;
    const float* Wrow0 = W + (size_t)(n0+srow[0])*DDIM + sc4[0]*4;
    const float* Wrow1 = W + (size_t)(n0+srow[1])*DDIM + sc4[1]*4;

    float acc[2][8][4];
    #pragma unroll
    for (int i=0;i<2;i++)
        #pragma unroll
        for (int j=0;j<8;j++)
            #pragma unroll
            for (int c=0;c<4;c++) acc[i][j][c]=0.f;

    float4 xr0 = *(const float4*)(Xrow0);
    float4 xr1 = *(const float4*)(Xrow1);
    float4 wr0 = *(const float4*)(Wrow0);
    float4 wr1 = *(const float4*)(Wrow1);
    *(uint4*)&Xs[0][srow[0]][sc4[0]*4] = make_uint4(f2tf(xr0.x),f2tf(xr0.y),f2tf(xr0.z),f2tf(xr0.w));
    *(uint4*)&Xs[0][srow[1]][sc4[1]*4] = make_uint4(f2tf(xr1.x),f2tf(xr1.y),f2tf(xr1.z),f2tf(xr1.w));
    *(uint4*)&Ws[0][srow[0]][sc4[0]*4] = make_uint4(f2tf(wr0.x),f2tf(wr0.y),f2tf(wr0.z),f2tf(wr0.w));
    *(uint4*)&Ws[0][srow[1]][sc4[1]*4] = make_uint4(f2tf(wr1.x),f2tf(wr1.y),f2tf(wr1.z),f2tf(wr1.w));
    __syncthreads();

    for (int t = 0; t < 64; t++){
        const int cur = t & 1;
        if (t + 1 < 64){
            const int kt = (t + 1) * 16;
            xr0 = *(const float4*)(Xrow0 + kt);
            xr1 = *(const float4*)(Xrow1 + kt);
            wr0 = *(const float4*)(Wrow0 + kt);
            wr1 = *(const float4*)(Wrow1 + kt);
        }

        #pragma unroll
        for (int ks=0; ks<2; ks++){
            const int kb = ks*8;
            uint32_t a[2][4], b[8][2];
            #pragma unroll
            for (int mt=0; mt<2; mt++){
                int r = wm*32 + mt*16;
                a[mt][0]=Xs[cur][r+g  ][kb+tig  ];
                a[mt][1]=Xs[cur][r+g+8][kb+tig  ];
                a[mt][2]=Xs[cur][r+g  ][kb+tig+4];
                a[mt][3]=Xs[cur][r+g+8][kb+tig+4];
            }
            #pragma unroll
            for (int nt=0; nt<8; nt++){
                int n = wn*64 + nt*8 + g;
                b[nt][0]=Ws[cur][n][kb+tig  ];
                b[nt][1]=Ws[cur][n][kb+tig+4];
            }
            #pragma unroll
            for (int mt=0;mt<2;mt++)
                #pragma unroll
                for (int nt=0;nt<8;nt++)
                    mma8(acc[mt][nt], a[mt], b[nt]);
        }

        if (t + 1 < 64){
            const int nxt = cur ^ 1;
            *(uint4*)&Xs[nxt][srow[0]][sc4[0]*4] = make_uint4(f2tf(xr0.x),f2tf(xr0.y),f2tf(xr0.z),f2tf(xr0.w));
            *(uint4*)&Xs[nxt][srow[1]][sc4[1]*4] = make_uint4(f2tf(xr1.x),f2tf(xr1.y),f2tf(xr1.z),f2tf(xr1.w));
            *(uint4*)&Ws[nxt][srow[0]][sc4[0]*4] = make_uint4(f2tf(wr0.x),f2tf(wr0.y),f2tf(wr0.z),f2tf(wr0.w));
            *(uint4*)&Ws[nxt][srow[1]][sc4[1]*4] = make_uint4(f2tf(wr1.x),f2tf(wr1.y),f2tf(wr1.z),f2tf(wr1.w));
            __syncthreads();
        }
    }

    const int h = (n0 >> 6) + wn;
    #pragma unroll
    for (int mt=0;mt<2;mt++){
        #pragma unroll
        for (int half=0; half<2; half++){
            int m  = m0 + wm*32 + mt*16 + g + half*8;
            int b_ = m >> 11;
            int s  = m & (SS-1);
            float* orow = Out + (((size_t)(b_*HH + h))*SS + s)*DH;
            #pragma unroll
            for (int nt=0; nt<8; nt++){
                int d = nt*8 + tig*2;
                float2 v;
                v.x = acc[mt][nt][half*2+0];
                v.y = acc[mt][nt][half*2+1];
                *(float2*)(orow + d) = v;
            }
        }
    }
}

// ============================================================================
// Flash attention v3: qblock=128, 4 warps, M=32/warp (R8 structure).
// R11: K/V staged via cp.async into DOUBLE-BUFFERED raw fp32 smem; tile t+1
// copies issue before tile t's compute -> staging latency hidden.
// cvt.rna moves to fragment-load time (bitwise-identical numerics).
// V is raw [s][d] (cp.async can't scatter) -> PV B-loads ~2-way conflicted.
// smem: K[2][64][68] | V[2][64][68] | Pb[128][68]  = 104448 B.
// ============================================================================
#define AT_PAD 68
#define KB_WORDS (64*AT_PAD)
#define VB_BASE  (2*KB_WORDS)
#define PB_BASE  (4*KB_WORDS)
#define AT_SMEM_WORDS (PB_BASE + 128*AT_PAD)
#define AT_SMEM_BYTES (AT_SMEM_WORDS*4)

__global__ __launch_bounds__(128) void attn_kernel(float* __restrict__ out){
    extern __shared__ uint32_t sm[];
    float*    fK = (float*)sm;              // [2][64][68] raw fp32 K tiles
    float*    fV = (float*)(sm + VB_BASE);  // [2][64][68] raw fp32 V tiles
    uint32_t* Pb = sm + PB_BASE;            // [128][68] Q (tf32), then P (tf32)
    const uint32_t sbase = (uint32_t)__cvta_generic_to_shared(sm);

    const int tid = threadIdx.x;
    const int w   = tid >> 5, lane = tid & 31;
    const int g   = lane >> 2, tig = lane & 3;
    const int q0  = blockIdx.x * 128;
    const int h   = blockIdx.y, b = blockIdx.z;
    const size_t headoff = ((size_t)(b*HH + h))*SS*DH;
    const float* Qg = g_Qh + headoff + (size_t)q0*DH;
    const float* Kg = g_Kh + headoff;
    const float* Vg = g_Vh + headoff;
    const float L2E = 1.44269504088896340736f;
    const float NEG_INF = __int_as_float(0xff800000);

    // Per-thread staging coordinates (8 chunks of 16B per 64x64 tile)
    int crow[8], cc4[8];
    #pragma unroll
    for (int i=0;i<8;i++){
        int idx = tid + i*128;
        crow[i] = idx >> 4;
        cc4[i]  = idx & 15;
    }

    // ---- Issue tile 0 K/V copies into buffer 0
    #pragma unroll
    for (int i=0;i<8;i++){
        uint32_t so = (uint32_t)(crow[i]*AT_PAD + cc4[i]*4) * 4u;
        cpa16(sbase + so,            Kg + (size_t)crow[i]*DH + cc4[i]*4);
        cpa16(sbase + VB_BASE*4 + so, Vg + (size_t)crow[i]*DH + cc4[i]*4);
    }
    CP_COMMIT();

    // ---- Stage Q (scaled by 0.125, tf32) into Pb: 128 rows x 16 float4
    #pragma unroll
    for (int i=0;i<16;i++){
        int idx = tid + i*128;
        int row = idx >> 4, c4 = idx & 15;
        float4 v = *(const float4*)(Qg + (size_t)row*DH + c4*4);
        *(uint4*)&Pb[row*AT_PAD + c4*4] =
            make_uint4(f2tf(v.x*0.125f), f2tf(v.y*0.125f),
                       f2tf(v.z*0.125f), f2tf(v.w*0.125f));
    }
    __syncthreads();
    uint32_t qa[2][8][4];
    #pragma unroll
    for (int mt=0; mt<2; mt++){
        const int r = w*32 + mt*16;
        #pragma unroll
        for (int ks=0; ks<8; ks++){
            int kb = ks*8;
            qa[mt][ks][0]=Pb[(r+g  )*AT_PAD + kb+tig  ];
            qa[mt][ks][1]=Pb[(r+g+8)*AT_PAD + kb+tig  ];
            qa[mt][ks][2]=Pb[(r+g  )*AT_PAD + kb+tig+4];
            qa[mt][ks][3]=Pb[(r+g+8)*AT_PAD + kb+tig+4];
        }
    }

    float Oacc[2][8][4];
    #pragma unroll
    for (int mt=0;mt<2;mt++)
        #pragma unroll
        for (int nt=0;nt<8;nt++)
            #pragma unroll
            for (int c=0;c<4;c++) Oacc[mt][nt][c]=0.f;
    float mr[2][2] = {{NEG_INF,NEG_INF},{NEG_INF,NEG_INF}};
    float lr[2][2] = {{0.f,0.f},{0.f,0.f}};

    for (int t = 0; t < 32; t++){
        const int cur = t & 1;
        const float* fKc = fK + cur*KB_WORDS;
        const float* fVc = fV + cur*KB_WORDS;

        CP_WAIT0();          // this thread's tile-t copies complete
        __syncthreads();     // all threads' copies visible; prev compute done

        // ---- Issue tile t+1 into the alternate buffer (overlaps compute)
        if (t + 1 < 32){
            const int nxt = cur ^ 1;
            const float* Kn = Kg + (size_t)(t+1)*64*DH;
            const float* Vn = Vg + (size_t)(t+1)*64*DH;
            #pragma unroll
            for (int i=0;i<8;i++){
                uint32_t so = (uint32_t)(nxt*KB_WORDS + crow[i]*AT_PAD + cc4[i]*4) * 4u;
                cpa16(sbase + so,             Kn + (size_t)crow[i]*DH + cc4[i]*4);
                cpa16(sbase + VB_BASE*4 + so, Vn + (size_t)crow[i]*DH + cc4[i]*4);
            }
            CP_COMMIT();
        }

        // ---- S = Q K^T : cvt-on-load B fragments, shared across M-tiles
        float S[2][8][4];
        #pragma unroll
        for (int mt=0;mt<2;mt++)
            #pragma unroll
            for (int nt=0;nt<8;nt++)
                #pragma unroll
                for (int c=0;c<4;c++) S[mt][nt][c]=0.f;
        #pragma unroll
        for (int ks=0; ks<8; ks++){
            const int kb = ks*8;
            #pragma unroll
            for (int nt=0; nt<8; nt++){
                uint32_t bfr[2];
                bfr[0]=f2tf(fKc[(nt*8+g)*AT_PAD + kb+tig  ]);
                bfr[1]=f2tf(fKc[(nt*8+g)*AT_PAD + kb+tig+4]);
                mma8(S[0][nt], qa[0][ks], bfr);
                mma8(S[1][nt], qa[1][ks], bfr);
            }
        }

        // ---- Online softmax per M-tile, then write P (warp-private rows)
        #pragma unroll
        for (int mt=0; mt<2; mt++){
            float rmax0 = NEG_INF, rmax1 = NEG_INF;
            #pragma unroll
            for (int nt=0;nt<8;nt++){
                rmax0 = fmaxf(rmax0, fmaxf(S[mt][nt][0], S[mt][nt][1]));
                rmax1 = fmaxf(rmax1, fmaxf(S[mt][nt][2], S[mt][nt][3]));
            }
            rmax0 = fmaxf(rmax0, __shfl_xor_sync(0xffffffffu, rmax0, 1));
            rmax0 = fmaxf(rmax0, __shfl_xor_sync(0xffffffffu, rmax0, 2));
            rmax1 = fmaxf(rmax1, __shfl_xor_sync(0xffffffffu, rmax1, 1));
            rmax1 = fmaxf(rmax1, __shfl_xor_sync(0xffffffffu, rmax1, 2));
            float mn0 = fmaxf(mr[mt][0], rmax0), mn1 = fmaxf(mr[mt][1], rmax1);
            float al0 = ex2f((mr[mt][0] - mn0)*L2E);
            float al1 = ex2f((mr[mt][1] - mn1)*L2E);
            mr[mt][0] = mn0; mr[mt][1] = mn1;

            float rs0 = 0.f, rs1 = 0.f;
            #pragma unroll
            for (int nt=0;nt<8;nt++){
                S[mt][nt][0] = ex2f((S[mt][nt][0]-mn0)*L2E); rs0 += S[mt][nt][0];
                S[mt][nt][1] = ex2f((S[mt][nt][1]-mn0)*L2E); rs0 += S[mt][nt][1];
                S[mt][nt][2] = ex2f((S[mt][nt][2]-mn1)*L2E); rs1 += S[mt][nt][2];
                S[mt][nt][3] = ex2f((S[mt][nt][3]-mn1)*L2E); rs1 += S[mt][nt][3];
            }
            rs0 += __shfl_xor_sync(0xffffffffu, rs0, 1);
            rs0 += __shfl_xor_sync(0xffffffffu, rs0, 2);
            rs1 += __shfl_xor_sync(0xffffffffu, rs1, 1);
            rs1 += __shfl_xor_sync(0xffffffffu, rs1, 2);
            lr[mt][0] = lr[mt][0]*al0 + rs0;
            lr[mt][1] = lr[mt][1]*al1 + rs1;
            #pragma unroll
            for (int nt=0;nt<8;nt++){
                Oacc[mt][nt][0]*=al0; Oacc[mt][nt][1]*=al0;
                Oacc[mt][nt][2]*=al1; Oacc[mt][nt][3]*=al1;
            }

            const int r = w*32 + mt*16;
            #pragma unroll
            for (int nt=0;nt<8;nt++){
                int c0 = nt*8 + tig*2;
                *(uint2*)&Pb[(r+g  )*AT_PAD + c0] =
                    make_uint2(f2tf(S[mt][nt][0]), f2tf(S[mt][nt][1]));
                *(uint2*)&Pb[(r+g+8)*AT_PAD + c0] =
                    make_uint2(f2tf(S[mt][nt][2]), f2tf(S[mt][nt][3]));
            }
        }
        __syncwarp();

        // ---- O += P V : bv cvt-on-load from raw V[s][d]
        #pragma unroll
        for (int ks=0; ks<8; ks++){
            const int kb = ks*8;
            uint32_t pa[2][4];
            #pragma unroll
            for (int mt=0; mt<2; mt++){
                const int r = w*32 + mt*16;
                pa[mt][0]=Pb[(r+g  )*AT_PAD + kb+tig  ];
                pa[mt][1]=Pb[(r+g+8)*AT_PAD + kb+tig  ];
                pa[mt][2]=Pb[(r+g  )*AT_PAD + kb+tig+4];
                pa[mt][3]=Pb[(r+g+8)*AT_PAD + kb+tig+4];
            }
            #pragma unroll
            for (int nt=0; nt<8; nt++){
                uint32_t bv[2];
                bv[0]=f2tf(fVc[(kb+tig  )*AT_PAD + nt*8+g]);
                bv[1]=f2tf(fVc[(kb+tig+4)*AT_PAD + nt*8+g]);
                mma8(Oacc[0][nt], pa[0], bv);
                mma8(Oacc[1][nt], pa[1], bv);
            }
        }
    }

    // ---- Epilogue: out[b, s, h*64+d] = O / l
    #pragma unroll
    for (int mt=0; mt<2; mt++){
        float inv0 = 1.f / lr[mt][0], inv1 = 1.f / lr[mt][1];
        int s0 = q0 + w*32 + mt*16 + g;
        #pragma unroll
        for (int nt=0;nt<8;nt++){
            int d = nt*8 + tig*2;
            float2 v0; v0.x = Oacc[mt][nt][0]*inv0; v0.y = Oacc[mt][nt][1]*inv0;
            *(float2*)(out + ((size_t)b*SS + s0  )*DDIM + h*DH + d) = v0;
            float2 v1; v1.x = Oacc[mt][nt][2]*inv1; v1.y = Oacc[mt][nt][3]*inv1;
            *(float2*)(out + ((size_t)b*SS + s0+8)*DDIM + h*DH + d) = v1;
        }
    }
}

extern "C" void kernel_launch(void* const* d_in, const int* in_sizes, int n_in,
                              void* d_out, int out_size){
    const float* q  = (const float*)d_in[0];
    const float* k  = (const float*)d_in[1];
    const float* v  = (const float*)d_in[2];
    const float* Wq = (const float*)d_in[3];
    const float* Wk = (const float*)d_in[4];
    const float* Wv = (const float*)d_in[5];

    dim3 pg(DDIM/128, MM/128, 3);  // (8, 64, 3) — fused Q/K/V projections
    proj_kernel<<<pg, 256>>>(q, k, v, Wq, Wk, Wv);

    cudaFuncSetAttribute(attn_kernel,
                         cudaFuncAttributeMaxDynamicSharedMemorySize,
                         AT_SMEM_BYTES);
    dim3 ag(SS/128, HH, BB);       // (16, 16, 4)
    attn_kernel<<<ag, 128, AT_SMEM_BYTES>>>((float*)d_out);
}